// round 9
// baseline (speedup 1.0000x reference)
#include <cuda_runtime.h>
#include <cstdint>

// Problem constants (fixed shapes for this problem instance)
#define DD     192          // projection dim
#define MM     128          // memory bank size
#define KT     256          // 2*MM prototypes
#define NMAX   131072       // 128*1024 rows
#define TINV   20.0f        // 1/temperature

// ---------------- device scratch (static; no allocation allowed) -----------
__device__ float g_E[(size_t)NMAX * KT];   // exp(sim/T), 128 MB
__device__ float g_pn[KT * DD];            // normalized prototypes
__device__ float g_gated[MM * DD];         // GLU(globalPrototypes) table
__device__ float g_invn[NMAX];             // 1/||x_i||
__device__ float g_cs1[KT], g_cs2[KT], g_cs3[KT];  // column sums per iteration
__device__ int   g_lastIdx[MM];            // last row assigned to each local proto

// packed f32x2 FMA: d.lo += a.lo*b.lo ; d.hi += a.hi*b.hi  (sm_103a FFMA2)
__device__ __forceinline__ void ffma2(unsigned long long& d,
                                      unsigned long long a,
                                      unsigned long long b) {
    asm("fma.rn.f32x2 %0, %1, %2, %0;" : "+l"(d) : "l"(a), "l"(b));
}
__device__ __forceinline__ unsigned long long dup2(float a) {
    unsigned long long r;
    asm("mov.b64 %0, {%1, %1};" : "=l"(r) : "f"(a));
    return r;
}
__device__ __forceinline__ void unpack2(unsigned long long v, float& lo, float& hi) {
    asm("mov.b64 {%0, %1}, %2;" : "=f"(lo), "=f"(hi) : "l"(v));
}
__device__ __forceinline__ unsigned long long pack2(float lo, float hi) {
    unsigned long long r;
    asm("mov.b64 %0, {%1, %2};" : "=l"(r) : "f"(lo), "f"(hi));
    return r;
}

// cp.async 16B chunk
__device__ __forceinline__ void cpa16(uint32_t saddr, const void* gaddr) {
    asm volatile("cp.async.cg.shared.global [%0], [%1], 16;"
                 :: "r"(saddr), "l"(gaddr));
}
__device__ __forceinline__ void cpa_commit() {
    asm volatile("cp.async.commit_group;");
}
template<int N>
__device__ __forceinline__ void cpa_wait() {
    asm volatile("cp.async.wait_group %0;" :: "n"(N));
}

// ---------------- setup: proto normalize + GLU table + resets --------------
__global__ void k_setup(const float* __restrict__ localP,
                        const float* __restrict__ globalP,
                        const float* __restrict__ W,
                        const float* __restrict__ bias) {
    int b = blockIdx.x;
    int t = threadIdx.x;           // 384 threads
    if (b < KT) {
        const float* src = (b < MM) ? (localP + b * DD) : (globalP + (b - MM) * DD);
        float v = (t < DD) ? src[t] : 0.0f;
        float ss = v * v;
        #pragma unroll
        for (int o = 16; o; o >>= 1) ss += __shfl_xor_sync(0xffffffffu, ss, o);
        __shared__ float tot;
        if (t == 0) tot = 0.0f;
        __syncthreads();
        if ((t & 31) == 0) atomicAdd(&tot, ss);
        __syncthreads();
        float rinv = rsqrtf(fmaxf(tot, 1e-12f));
        if (t < DD) g_pn[b * DD + t] = v * rinv;
    } else if (b < KT + MM) {
        // GLU table row m: lin = G[m] @ W + b ; gated = lin[:D]*sigmoid(lin[D:])
        int m = b - KT;
        __shared__ float gp[DD];
        __shared__ float lin[2 * DD];
        if (t < DD) gp[t] = globalP[m * DD + t];
        __syncthreads();
        float acc = bias[t];
        for (int k = 0; k < DD; k++) acc += gp[k] * W[k * (2 * DD) + t];
        lin[t] = acc;
        __syncthreads();
        if (t < DD) {
            float z = lin[t + DD];
            float sig = 1.0f / (1.0f + __expf(-z));
            g_gated[m * DD + t] = lin[t] * sig;
        }
    } else {
        // resets (must re-run on every graph replay)
        if (t < KT) { g_cs1[t] = 0.0f; g_cs2[t] = 0.0f; g_cs3[t] = 0.0f; }
        if (t < MM) g_lastIdx[t] = -1;
    }
}

// ---------------- row inverse norms of x -----------------------------------
__global__ void k_rownorm(const float* __restrict__ x, int n) {
    int lane = threadIdx.x & 31;
    int warp = (blockIdx.x * blockDim.x + threadIdx.x) >> 5;
    int nw   = (gridDim.x * blockDim.x) >> 5;
    for (int row = warp; row < n; row += nw) {
        const float* xr = x + (size_t)row * DD;
        float ss = 0.0f;
        #pragma unroll
        for (int k = 0; k < 6; k++) { float v = xr[lane + 32 * k]; ss += v * v; }
        #pragma unroll
        for (int o = 16; o; o >>= 1) ss += __shfl_xor_sync(0xffffffffu, ss, o);
        if (lane == 0) g_invn[row] = rsqrtf(fmaxf(ss, 1e-12f));
    }
}

// ---------------- GEMM: E = exp(sim/T), row factor a1, colsum1 -------------
// C tile 64x256, 256 threads, thread tile 4 rows x 16 cols, FFMA2 core.
// x tile double-buffered via cp.async (row-major; A-loads are broadcasts).
// ps tile float-swizzled (col c at c + 2*(c>>4)) -> conflict-free LDS.64.
#define BR 64
#define KC 48
#define NSTG 4                  // 192 / 48
#define XSP 52                  // xs row stride (floats), 208 B = 13*16B
#define PSS 290                 // ps row stride; 290*4 mod 128 = 8
__global__ __launch_bounds__(256, 2)
void k_gemm(const float* __restrict__ x, int n) {
    __shared__ __align__(16) float xs[2][BR][XSP];   // 2 x 13.3 KB
    __shared__ __align__(16) float ps[KC][PSS];      // 55.7 KB
    __shared__ float a_s[BR];

    int tid = threadIdx.x;
    int tr = tid >> 4;                    // 0..15 row group
    int tc = tid & 15;                    // 0..15 col group
    int r0 = blockIdx.x * BR;

    unsigned long long acc2[4][8];        // packed f32x2 accumulators
    #pragma unroll
    for (int i = 0; i < 4; i++)
        #pragma unroll
        for (int j = 0; j < 8; j++) acc2[i][j] = 0ull;

    // issue xs stage 0  (3 x 16B chunks per thread: 64 rows x 12 chunks)
    {
        uint32_t sb = (uint32_t)__cvta_generic_to_shared(&xs[0][0][0]);
        #pragma unroll
        for (int i = 0; i < 3; i++) {
            int ch = tid + i * 256;
            int r = ch / 12, kc = ch - r * 12;
            cpa16(sb + (uint32_t)(r * XSP + kc * 4) * 4,
                  x + (size_t)(r0 + r) * DD + kc * 4);
        }
        cpa_commit();
    }

    for (int s = 0; s < NSTG; s++) {
        int k0 = s * KC;
        if (s < NSTG - 1) {    // prefetch next x stage into other buffer
            uint32_t sb = (uint32_t)__cvta_generic_to_shared(&xs[(s + 1) & 1][0][0]);
            int kn = k0 + KC;
            #pragma unroll
            for (int i = 0; i < 3; i++) {
                int ch = tid + i * 256;
                int r = ch / 12, kc = ch - r * 12;
                cpa16(sb + (uint32_t)(r * XSP + kc * 4) * 4,
                      x + (size_t)(r0 + r) * DD + kn + kc * 4);
            }
            cpa_commit();
        }
        // ps for this stage: thread = column c; 12 LDG.128, conflict-free STS
        {
            int c = tid;
            int cc = c + ((c >> 4) << 1);
            const float4* src = (const float4*)(g_pn + c * DD + k0);
            #pragma unroll
            for (int kc = 0; kc < 12; kc++) {
                float4 v = src[kc];
                ps[kc * 4 + 0][cc] = v.x;
                ps[kc * 4 + 1][cc] = v.y;
                ps[kc * 4 + 2][cc] = v.z;
                ps[kc * 4 + 3][cc] = v.w;
            }
        }
        if (s < NSTG - 1) cpa_wait<1>(); else cpa_wait<0>();
        __syncthreads();

        const float (*xb)[XSP] = xs[s & 1];
        #pragma unroll 8
        for (int kk = 0; kk < KC; kk++) {
            unsigned long long av[4];
            #pragma unroll
            for (int i = 0; i < 4; i++) av[i] = dup2(xb[tr * 4 + i][kk]);
            const unsigned long long* bp =
                (const unsigned long long*)&ps[kk][tc * 18];      // swizzled base
            #pragma unroll
            for (int j = 0; j < 8; j++) {
                unsigned long long b = bp[j];
                ffma2(acc2[0][j], av[0], b);
                ffma2(acc2[1][j], av[1], b);
                ffma2(acc2[2][j], av[2], b);
                ffma2(acc2[3][j], av[3], b);
            }
        }
        __syncthreads();
    }

    // epilogue: normalize row, exponentiate, rowsum; store E; repack exps
    float rsum[4] = {0.f, 0.f, 0.f, 0.f};
    float sc[4];
    #pragma unroll
    for (int i = 0; i < 4; i++) sc[i] = g_invn[r0 + tr * 4 + i] * TINV;
    #pragma unroll
    for (int i = 0; i < 4; i++) {
        float2* dst = (float2*)(g_E + (size_t)(r0 + tr * 4 + i) * KT + tc * 16);
        #pragma unroll
        for (int j = 0; j < 8; j++) {
            float lo, hi;
            unpack2(acc2[i][j], lo, hi);
            float e0 = __expf(lo * sc[i]);
            float e1 = __expf(hi * sc[i]);
            rsum[i] += e0 + e1;
            acc2[i][j] = pack2(e0, e1);
            dst[j] = make_float2(e0, e1);
        }
    }

    // a1_i = 1/(n * rowsum_i)   (red overlays xs[0] — dead after the k loop)
    float (*red)[17] = (float (*)[17])&xs[0][0][0];
    #pragma unroll
    for (int i = 0; i < 4; i++) red[tr * 4 + i][tc] = rsum[i];
    __syncthreads();
    if (tid < BR) {
        float s = 0.0f;
        #pragma unroll
        for (int j = 0; j < 16; j++) s += red[tid][j];
        a_s[tid] = 1.0f / ((float)n * s);
    }
    __syncthreads();

    // colsum1_j += sum_rows a1_i * E_ij   (block-local reduce, one atomic/col)
    float* cred = &ps[0][0];              // reuse ps smem as [16][256]
    #pragma unroll
    for (int j = 0; j < 8; j++) {
        float s0 = 0.0f, s1 = 0.0f;
        #pragma unroll
        for (int i = 0; i < 4; i++) {
            float lo, hi;
            unpack2(acc2[i][j], lo, hi);
            float a = a_s[tr * 4 + i];
            s0 += a * lo;
            s1 += a * hi;
        }
        cred[tr * 256 + tc * 16 + 2 * j]     = s0;
        cred[tr * 256 + tc * 16 + 2 * j + 1] = s1;
    }
    __syncthreads();
    {
        int c = tid;                      // 256 threads, 256 cols
        float s = 0.0f;
        #pragma unroll
        for (int g = 0; g < 16; g++) s += cred[g * 256 + c];
        atomicAdd(&g_cs1[c], s);
    }
}

// ---------------- sinkhorn pass: b from cs_in; a per-row; accumulate cs_out
// 8 rows per warp iteration: 16 LDG.128 in flight before the reduce chains.
template<int P>
__global__ void k_pass(int n) {
    const float* csin  = (P == 1) ? g_cs1 : g_cs2;
    float*       csout = (P == 1) ? g_cs2 : g_cs3;
    int lane = threadIdx.x & 31;
    int warp = (blockIdx.x * blockDim.x + threadIdx.x) >> 5;
    int nw   = (gridDim.x * blockDim.x) >> 5;

    float bb[8];
    #pragma unroll
    for (int j = 0; j < 8; j++) bb[j] = 1.0f / ((float)KT * csin[lane * 8 + j]);

    float cacc[8] = {0.f, 0.f, 0.f, 0.f, 0.f, 0.f, 0.f, 0.f};
    float ninv = 1.0f / (float)n;
    for (int rg = warp * 8; rg < n; rg += nw * 8) {
        float4 e[8][2];
        #pragma unroll
        for (int r = 0; r < 8; r++) {
            const float4* er = (const float4*)(g_E + (size_t)(rg + r) * KT) + lane * 2;
            e[r][0] = er[0]; e[r][1] = er[1];
        }
        #pragma unroll
        for (int r = 0; r < 8; r++) {
            float s = e[r][0].x * bb[0] + e[r][0].y * bb[1] + e[r][0].z * bb[2] + e[r][0].w * bb[3]
                    + e[r][1].x * bb[4] + e[r][1].y * bb[5] + e[r][1].z * bb[6] + e[r][1].w * bb[7];
            #pragma unroll
            for (int o = 16; o; o >>= 1) s += __shfl_xor_sync(0xffffffffu, s, o);
            float a = ninv / s;
            cacc[0] += a * e[r][0].x; cacc[1] += a * e[r][0].y;
            cacc[2] += a * e[r][0].z; cacc[3] += a * e[r][0].w;
            cacc[4] += a * e[r][1].x; cacc[5] += a * e[r][1].y;
            cacc[6] += a * e[r][1].z; cacc[7] += a * e[r][1].w;
        }
    }
    __shared__ float sacc[KT];
    if (threadIdx.x < KT) sacc[threadIdx.x] = 0.0f;
    __syncthreads();
    #pragma unroll
    for (int j = 0; j < 8; j++) atomicAdd(&sacc[lane * 8 + j], cacc[j]);
    __syncthreads();
    if (threadIdx.x < KT) atomicAdd(&csout[threadIdx.x], sacc[threadIdx.x]);
}

// ---------------- final: argmaxes, output blend+normalize, lastIdx ---------
__global__ void k_final(const float* __restrict__ x, float* __restrict__ out, int n) {
    int lane = threadIdx.x & 31;
    int warp = (blockIdx.x * blockDim.x + threadIdx.x) >> 5;
    int nw   = (gridDim.x * blockDim.x) >> 5;

    float bb[8];
    #pragma unroll
    for (int j = 0; j < 8; j++) bb[j] = 1.0f / ((float)KT * g_cs3[lane * 8 + j]);

    for (int rg = warp * 4; rg < n; rg += nw * 4) {
        float4 e[4][2];
        #pragma unroll
        for (int r = 0; r < 4; r++) {
            const float4* er = (const float4*)(g_E + (size_t)(rg + r) * KT) + lane * 2;
            e[r][0] = er[0]; e[r][1] = er[1];
        }
        #pragma unroll
        for (int r = 0; r < 4; r++) {
            int row = rg + r;
            float v[8] = { e[r][0].x * bb[0], e[r][0].y * bb[1], e[r][0].z * bb[2], e[r][0].w * bb[3],
                           e[r][1].x * bb[4], e[r][1].y * bb[5], e[r][1].z * bb[6], e[r][1].w * bb[7] };
            float best = v[0]; int bi = lane * 8;
            #pragma unroll
            for (int j = 1; j < 8; j++)
                if (v[j] > best) { best = v[j]; bi = lane * 8 + j; }
            // reduce within 16-lane halves (lanes 0..15: local cols, 16..31: global)
            #pragma unroll
            for (int o = 1; o < 16; o <<= 1) {
                float ob = __shfl_xor_sync(0xffffffffu, best, o);
                int  obi = __shfl_xor_sync(0xffffffffu, bi, o);
                if (ob > best || (ob == best && obi < bi)) { best = ob; bi = obi; }
            }
            int lidx = __shfl_sync(0xffffffffu, bi, 0);         // 0..127 (first occurrence)
            int gidx = __shfl_sync(0xffffffffu, bi, 16) - MM;   // 0..127
            if (lane == 0) atomicMax(&g_lastIdx[lidx], row);    // last-write-wins

            const float* xr = x + (size_t)row * DD;
            const float* gt = g_gated + (size_t)gidx * DD;
            float o6[6]; float ss = 0.0f;
            #pragma unroll
            for (int k = 0; k < 6; k++) {
                float ov = 0.5f * (gt[lane + 32 * k] + xr[lane + 32 * k]);
                o6[k] = ov; ss += ov * ov;
            }
            #pragma unroll
            for (int o = 16; o; o >>= 1) ss += __shfl_xor_sync(0xffffffffu, ss, o);
            float rinv = rsqrtf(fmaxf(ss, 1e-12f));
            float* orow = out + (size_t)row * DD;
            #pragma unroll
            for (int k = 0; k < 6; k++) orow[lane + 32 * k] = o6[k] * rinv;
        }
    }
}

// ---------------- EMA finalize: last-write-wins scatter --------------------
__global__ void k_ema(const float* __restrict__ x,
                      const float* __restrict__ localP,
                      float* __restrict__ outLocal) {
    int m = blockIdx.x;
    int t = threadIdx.x;   // 192
    int i = g_lastIdx[m];
    float lv = localP[m * DD + t];
    float v = (i >= 0) ? (0.96f * lv + (1.0f - 0.96f) * x[(size_t)i * DD + t]) : lv;
    outLocal[m * DD + t] = v;
}

// ---------------- launcher -------------------------------------------------
extern "C" void kernel_launch(void* const* d_in, const int* in_sizes, int n_in,
                              void* d_out, int out_size) {
    const float* proj    = (const float*)d_in[0];
    const float* localP  = (const float*)d_in[1];
    const float* globalP = (const float*)d_in[2];
    const float* W       = (const float*)d_in[3];
    const float* bias    = (const float*)d_in[4];
    float* out = (float*)d_out;

    int n = in_sizes[0] / DD;        // 131072
    float* outLocal = out + (size_t)in_sizes[0];

    k_setup<<<KT + MM + 1, 2 * DD>>>(localP, globalP, W, bias);
    k_rownorm<<<512, 256>>>(proj, n);
    k_gemm<<<n / BR, 256>>>(proj, n);
    k_pass<1><<<1024, 256>>>(n);
    k_pass<2><<<1024, 256>>>(n);
    k_final<<<1024, 256>>>(proj, out, n);
    k_ema<<<MM, DD>>>(proj, localP, outLocal);
}

// round 10
// speedup vs baseline: 1.2857x; 1.2857x over previous
#include <cuda_runtime.h>
#include <cstdint>

// Problem constants (fixed shapes for this problem instance)
#define DD     192          // projection dim
#define MM     128          // memory bank size
#define KT     256          // 2*MM prototypes
#define NMAX   131072       // 128*1024 rows
#define TINV   20.0f        // 1/temperature

#define PSS    288          // swizzled proto row stride (floats); 1152 B = 9*128
#define KC     32
#define NSTG   6            // 192 / 32
#define BR     64
#define XSP    36           // xs row stride (floats), 144 B = 9*16

// ---------------- device scratch (static; no allocation allowed) -----------
__device__ float g_E[(size_t)NMAX * KT];   // exp(sim/T), 128 MB
__device__ __align__(16) float g_pnT[DD * PSS];  // transposed+swizzled protos
__device__ float g_gated[MM * DD];         // GLU(globalPrototypes) table
__device__ float g_invn[NMAX];             // 1/||x_i||
__device__ float g_cs1[KT], g_cs2[KT], g_cs3[KT];  // column sums per iteration
__device__ int   g_lastIdx[MM];            // last row assigned to each local proto

// packed f32x2 FMA: d.lo += a.lo*b.lo ; d.hi += a.hi*b.hi  (sm_103a FFMA2)
__device__ __forceinline__ void ffma2(unsigned long long& d,
                                      unsigned long long a,
                                      unsigned long long b) {
    asm("fma.rn.f32x2 %0, %1, %2, %0;" : "+l"(d) : "l"(a), "l"(b));
}
__device__ __forceinline__ unsigned long long dup2(float a) {
    unsigned long long r;
    asm("mov.b64 %0, {%1, %1};" : "=l"(r) : "f"(a));
    return r;
}
__device__ __forceinline__ void unpack2(unsigned long long v, float& lo, float& hi) {
    asm("mov.b64 {%0, %1}, %2;" : "=f"(lo), "=f"(hi) : "l"(v));
}
__device__ __forceinline__ unsigned long long pack2(float lo, float hi) {
    unsigned long long r;
    asm("mov.b64 %0, {%1, %2};" : "=l"(r) : "f"(lo), "f"(hi));
    return r;
}

// cp.async 16B chunk
__device__ __forceinline__ void cpa16(uint32_t saddr, const void* gaddr) {
    asm volatile("cp.async.cg.shared.global [%0], [%1], 16;"
                 :: "r"(saddr), "l"(gaddr));
}
__device__ __forceinline__ void cpa_commit() {
    asm volatile("cp.async.commit_group;");
}
template<int N>
__device__ __forceinline__ void cpa_wait() {
    asm volatile("cp.async.wait_group %0;" :: "n"(N));
}

// ---------------- setup: proto normalize(+transpose) + GLU table + resets --
__global__ void k_setup(const float* __restrict__ localP,
                        const float* __restrict__ globalP,
                        const float* __restrict__ W,
                        const float* __restrict__ bias) {
    int b = blockIdx.x;
    int t = threadIdx.x;           // 384 threads
    if (b < KT) {
        const float* src = (b < MM) ? (localP + b * DD) : (globalP + (b - MM) * DD);
        float v = (t < DD) ? src[t] : 0.0f;
        float ss = v * v;
        #pragma unroll
        for (int o = 16; o; o >>= 1) ss += __shfl_xor_sync(0xffffffffu, ss, o);
        __shared__ float tot;
        if (t == 0) tot = 0.0f;
        __syncthreads();
        if ((t & 31) == 0) atomicAdd(&tot, ss);
        __syncthreads();
        float rinv = rsqrtf(fmaxf(tot, 1e-12f));
        // transposed, bank-swizzled store: row=k, col = b + 2*(b>>4)
        if (t < DD) g_pnT[t * PSS + b + ((b >> 4) << 1)] = v * rinv;
    } else if (b < KT + MM) {
        // GLU table row m: lin = G[m] @ W + b ; gated = lin[:D]*sigmoid(lin[D:])
        int m = b - KT;
        __shared__ float gp[DD];
        __shared__ float lin[2 * DD];
        if (t < DD) gp[t] = globalP[m * DD + t];
        __syncthreads();
        float acc = bias[t];
        for (int k = 0; k < DD; k++) acc += gp[k] * W[k * (2 * DD) + t];
        lin[t] = acc;
        __syncthreads();
        if (t < DD) {
            float z = lin[t + DD];
            float sig = 1.0f / (1.0f + __expf(-z));
            g_gated[m * DD + t] = lin[t] * sig;
        }
    } else {
        // resets (must re-run on every graph replay)
        if (t < KT) { g_cs1[t] = 0.0f; g_cs2[t] = 0.0f; g_cs3[t] = 0.0f; }
        if (t < MM) g_lastIdx[t] = -1;
    }
}

// ---------------- row inverse norms of x -----------------------------------
__global__ void k_rownorm(const float* __restrict__ x, int n) {
    int lane = threadIdx.x & 31;
    int warp = (blockIdx.x * blockDim.x + threadIdx.x) >> 5;
    int nw   = (gridDim.x * blockDim.x) >> 5;
    for (int row = warp; row < n; row += nw) {
        const float* xr = x + (size_t)row * DD;
        float ss = 0.0f;
        #pragma unroll
        for (int k = 0; k < 6; k++) { float v = xr[lane + 32 * k]; ss += v * v; }
        #pragma unroll
        for (int o = 16; o; o >>= 1) ss += __shfl_xor_sync(0xffffffffu, ss, o);
        if (lane == 0) g_invn[row] = rsqrtf(fmaxf(ss, 1e-12f));
    }
}

// ---------------- GEMM: E = exp(sim/T), row factor a1, colsum1 -------------
// C tile 64x256, 256 threads, thread tile 4 rows x 16 cols, FFMA2 core.
// Both tiles double-buffered via cp.async; ps stages are CONTIGUOUS copies
// from the pre-transposed+swizzled g_pnT (coalesced, no transpose on load).
__global__ __launch_bounds__(256, 2)
void k_gemm(const float* __restrict__ x, int n) {
    __shared__ __align__(16) float xs[2][BR * XSP];     // 2 x 9.2 KB
    __shared__ __align__(16) float ps[2][KC * PSS];     // 2 x 36.9 KB
    __shared__ float a_s[BR];

    int tid = threadIdx.x;
    int tr = tid >> 4;                    // 0..15 row group
    int tc = tid & 15;                    // 0..15 col group
    int r0 = blockIdx.x * BR;

    unsigned long long acc2[4][8];        // packed f32x2 accumulators
    #pragma unroll
    for (int i = 0; i < 4; i++)
        #pragma unroll
        for (int j = 0; j < 8; j++) acc2[i][j] = 0ull;

    uint32_t xs_sb[2], ps_sb[2];
    #pragma unroll
    for (int bfi = 0; bfi < 2; bfi++) {
        xs_sb[bfi] = (uint32_t)__cvta_generic_to_shared(&xs[bfi][0]);
        ps_sb[bfi] = (uint32_t)__cvta_generic_to_shared(&ps[bfi][0]);
    }

    // per-thread chunk coords for xs (2 chunks: 64 rows x 8 chunks of 16B)
    int xr0 = tid >> 2,        xk0 = (tid & 3);            // chunk (r, kc) pair 1
    int xr1 = (tid + 256) >> 2, xk1 = ((tid + 256) & 3);   // pair 2 (kc 4..7)
    // note: 512 chunks = 64 rows * 8; mapping: ch = r*8 + kc? use simple:
    // ch0 = tid -> r=tid>>2? that gives kc 0..3 only. Use ch = tid and tid+256:
    // r = ch >> 3, kc = ch & 7.
    xr0 = tid >> 3;        xk0 = tid & 7;
    xr1 = (tid + 256) >> 3; xk1 = (tid + 256) & 7;

    auto issue_stage = [&](int s) {
        int k0 = s * KC;
        int bfi = s & 1;
        // xs: 64 rows x 32 floats, row stride XSP
        cpa16(xs_sb[bfi] + (uint32_t)(xr0 * XSP + xk0 * 4) * 4,
              x + (size_t)(r0 + xr0) * DD + k0 + xk0 * 4);
        cpa16(xs_sb[bfi] + (uint32_t)(xr1 * XSP + xk1 * 4) * 4,
              x + (size_t)(r0 + xr1) * DD + k0 + xk1 * 4);
        // ps: one contiguous 32*PSS-float block from g_pnT
        const float* src = g_pnT + (size_t)k0 * PSS;
        #pragma unroll
        for (int i = 0; i < 9; i++) {
            int ch = tid + i * 256;       // 2304 chunks of 16B
            cpa16(ps_sb[bfi] + (uint32_t)ch * 16, src + ch * 4);
        }
        cpa_commit();
    };

    issue_stage(0);

    for (int s = 0; s < NSTG; s++) {
        if (s + 1 < NSTG) { issue_stage(s + 1); cpa_wait<1>(); }
        else              { cpa_wait<0>(); }
        __syncthreads();

        const float* xb = &xs[s & 1][0];
        const float* pb = &ps[s & 1][0];
        #pragma unroll
        for (int kk = 0; kk < KC; kk++) {
            unsigned long long av[4];
            #pragma unroll
            for (int i = 0; i < 4; i++) av[i] = dup2(xb[(tr * 4 + i) * XSP + kk]);
            const unsigned long long* bp =
                (const unsigned long long*)&pb[kk * PSS + tc * 18];  // swizzled base
            #pragma unroll
            for (int j = 0; j < 8; j++) {
                unsigned long long b = bp[j];
                ffma2(acc2[0][j], av[0], b);
                ffma2(acc2[1][j], av[1], b);
                ffma2(acc2[2][j], av[2], b);
                ffma2(acc2[3][j], av[3], b);
            }
        }
        __syncthreads();
    }

    // epilogue: normalize row, exponentiate, rowsum; store E; repack exps
    float rsum[4] = {0.f, 0.f, 0.f, 0.f};
    float sc[4];
    #pragma unroll
    for (int i = 0; i < 4; i++) sc[i] = g_invn[r0 + tr * 4 + i] * TINV;
    #pragma unroll
    for (int i = 0; i < 4; i++) {
        float2* dst = (float2*)(g_E + (size_t)(r0 + tr * 4 + i) * KT + tc * 16);
        #pragma unroll
        for (int j = 0; j < 8; j++) {
            float lo, hi;
            unpack2(acc2[i][j], lo, hi);
            float e0 = __expf(lo * sc[i]);
            float e1 = __expf(hi * sc[i]);
            rsum[i] += e0 + e1;
            acc2[i][j] = pack2(e0, e1);
            dst[j] = make_float2(e0, e1);
        }
    }

    // a1_i = 1/(n * rowsum_i)   (red overlays xs — dead after the k loop)
    float (*red)[17] = (float (*)[17])&xs[0][0];
    #pragma unroll
    for (int i = 0; i < 4; i++) red[tr * 4 + i][tc] = rsum[i];
    __syncthreads();
    if (tid < BR) {
        float s = 0.0f;
        #pragma unroll
        for (int j = 0; j < 16; j++) s += red[tid][j];
        a_s[tid] = 1.0f / ((float)n * s);
    }
    __syncthreads();

    // colsum1_j += sum_rows a1_i * E_ij   (block-local reduce, one atomic/col)
    float* cred = &ps[0][0];              // reuse ps smem as [16][256]
    #pragma unroll
    for (int j = 0; j < 8; j++) {
        float s0 = 0.0f, s1 = 0.0f;
        #pragma unroll
        for (int i = 0; i < 4; i++) {
            float lo, hi;
            unpack2(acc2[i][j], lo, hi);
            float a = a_s[tr * 4 + i];
            s0 += a * lo;
            s1 += a * hi;
        }
        cred[tr * 256 + tc * 16 + 2 * j]     = s0;
        cred[tr * 256 + tc * 16 + 2 * j + 1] = s1;
    }
    __syncthreads();
    {
        int c = tid;                      // 256 threads, 256 cols
        float s = 0.0f;
        #pragma unroll
        for (int g = 0; g < 16; g++) s += cred[g * 256 + c];
        atomicAdd(&g_cs1[c], s);
    }
}

// ---------------- sinkhorn pass: b from cs_in; a per-row; accumulate cs_out
// 4 rows per warp iteration: 8 LDG.128 in flight before the reduce chains.
template<int P>
__global__ void k_pass(int n) {
    const float* csin  = (P == 1) ? g_cs1 : g_cs2;
    float*       csout = (P == 1) ? g_cs2 : g_cs3;
    int lane = threadIdx.x & 31;
    int warp = (blockIdx.x * blockDim.x + threadIdx.x) >> 5;
    int nw   = (gridDim.x * blockDim.x) >> 5;

    float bb[8];
    #pragma unroll
    for (int j = 0; j < 8; j++) bb[j] = 1.0f / ((float)KT * csin[lane * 8 + j]);

    float cacc[8] = {0.f, 0.f, 0.f, 0.f, 0.f, 0.f, 0.f, 0.f};
    float ninv = 1.0f / (float)n;
    for (int rg = warp * 4; rg < n; rg += nw * 4) {
        float4 e[4][2];
        #pragma unroll
        for (int r = 0; r < 4; r++) {
            const float4* er = (const float4*)(g_E + (size_t)(rg + r) * KT) + lane * 2;
            e[r][0] = er[0]; e[r][1] = er[1];
        }
        #pragma unroll
        for (int r = 0; r < 4; r++) {
            float s = e[r][0].x * bb[0] + e[r][0].y * bb[1] + e[r][0].z * bb[2] + e[r][0].w * bb[3]
                    + e[r][1].x * bb[4] + e[r][1].y * bb[5] + e[r][1].z * bb[6] + e[r][1].w * bb[7];
            #pragma unroll
            for (int o = 16; o; o >>= 1) s += __shfl_xor_sync(0xffffffffu, s, o);
            float a = ninv / s;
            cacc[0] += a * e[r][0].x; cacc[1] += a * e[r][0].y;
            cacc[2] += a * e[r][0].z; cacc[3] += a * e[r][0].w;
            cacc[4] += a * e[r][1].x; cacc[5] += a * e[r][1].y;
            cacc[6] += a * e[r][1].z; cacc[7] += a * e[r][1].w;
        }
    }
    __shared__ float sacc[KT];
    if (threadIdx.x < KT) sacc[threadIdx.x] = 0.0f;
    __syncthreads();
    #pragma unroll
    for (int j = 0; j < 8; j++) atomicAdd(&sacc[lane * 8 + j], cacc[j]);
    __syncthreads();
    if (threadIdx.x < KT) atomicAdd(&csout[threadIdx.x], sacc[threadIdx.x]);
}

// ---------------- final: argmaxes, output blend+normalize, lastIdx ---------
__global__ void k_final(const float* __restrict__ x, float* __restrict__ out, int n) {
    int lane = threadIdx.x & 31;
    int warp = (blockIdx.x * blockDim.x + threadIdx.x) >> 5;
    int nw   = (gridDim.x * blockDim.x) >> 5;

    float bb[8];
    #pragma unroll
    for (int j = 0; j < 8; j++) bb[j] = 1.0f / ((float)KT * g_cs3[lane * 8 + j]);

    for (int rg = warp * 2; rg < n; rg += nw * 2) {
        float4 e[2][2];
        #pragma unroll
        for (int r = 0; r < 2; r++) {
            const float4* er = (const float4*)(g_E + (size_t)(rg + r) * KT) + lane * 2;
            e[r][0] = er[0]; e[r][1] = er[1];
        }
        #pragma unroll
        for (int r = 0; r < 2; r++) {
            int row = rg + r;
            float v[8] = { e[r][0].x * bb[0], e[r][0].y * bb[1], e[r][0].z * bb[2], e[r][0].w * bb[3],
                           e[r][1].x * bb[4], e[r][1].y * bb[5], e[r][1].z * bb[6], e[r][1].w * bb[7] };
            float best = v[0]; int bi = lane * 8;
            #pragma unroll
            for (int j = 1; j < 8; j++)
                if (v[j] > best) { best = v[j]; bi = lane * 8 + j; }
            // reduce within 16-lane halves (lanes 0..15: local cols, 16..31: global)
            #pragma unroll
            for (int o = 1; o < 16; o <<= 1) {
                float ob = __shfl_xor_sync(0xffffffffu, best, o);
                int  obi = __shfl_xor_sync(0xffffffffu, bi, o);
                if (ob > best || (ob == best && obi < bi)) { best = ob; bi = obi; }
            }
            int lidx = __shfl_sync(0xffffffffu, bi, 0);         // 0..127 (first occurrence)
            int gidx = __shfl_sync(0xffffffffu, bi, 16) - MM;   // 0..127
            if (lane == 0) atomicMax(&g_lastIdx[lidx], row);    // last-write-wins

            const float* xr = x + (size_t)row * DD;
            const float* gt = g_gated + (size_t)gidx * DD;
            float o6[6]; float ss = 0.0f;
            #pragma unroll
            for (int k = 0; k < 6; k++) {
                float ov = 0.5f * (gt[lane + 32 * k] + xr[lane + 32 * k]);
                o6[k] = ov; ss += ov * ov;
            }
            #pragma unroll
            for (int o = 16; o; o >>= 1) ss += __shfl_xor_sync(0xffffffffu, ss, o);
            float rinv = rsqrtf(fmaxf(ss, 1e-12f));
            float* orow = out + (size_t)row * DD;
            #pragma unroll
            for (int k = 0; k < 6; k++) orow[lane + 32 * k] = o6[k] * rinv;
        }
    }
}

// ---------------- EMA finalize: last-write-wins scatter --------------------
__global__ void k_ema(const float* __restrict__ x,
                      const float* __restrict__ localP,
                      float* __restrict__ outLocal) {
    int m = blockIdx.x;
    int t = threadIdx.x;   // 192
    int i = g_lastIdx[m];
    float lv = localP[m * DD + t];
    float v = (i >= 0) ? (0.96f * lv + (1.0f - 0.96f) * x[(size_t)i * DD + t]) : lv;
    outLocal[m * DD + t] = v;
}

// ---------------- launcher -------------------------------------------------
extern "C" void kernel_launch(void* const* d_in, const int* in_sizes, int n_in,
                              void* d_out, int out_size) {
    const float* proj    = (const float*)d_in[0];
    const float* localP  = (const float*)d_in[1];
    const float* globalP = (const float*)d_in[2];
    const float* W       = (const float*)d_in[3];
    const float* bias    = (const float*)d_in[4];
    float* out = (float*)d_out;

    int n = in_sizes[0] / DD;        // 131072
    float* outLocal = out + (size_t)in_sizes[0];

    k_setup<<<KT + MM + 1, 2 * DD>>>(localP, globalP, W, bias);
    k_rownorm<<<512, 256>>>(proj, n);
    k_gemm<<<n / BR, 256>>>(proj, n);
    k_pass<1><<<1024, 256>>>(n);
    k_pass<2><<<1024, 256>>>(n);
    k_final<<<1024, 256>>>(proj, out, n);
    k_ema<<<MM, DD>>>(proj, localP, outLocal);
}

// round 11
// speedup vs baseline: 1.3888x; 1.0802x over previous
#include <cuda_runtime.h>
#include <cstdint>

// Problem constants (fixed shapes for this problem instance)
#define DD     192          // projection dim
#define MM     128          // memory bank size
#define KT     256          // 2*MM prototypes
#define NMAX   131072       // 128*1024 rows
#define TINV   20.0f        // 1/temperature

#define PSS    288          // swizzled proto row stride (floats); 1152 B = 9*128
#define KC     32
#define NSTG   6            // 192 / 32
#define BR     128          // block row tile
#define XSP    36           // xs row stride (floats), 144 B = 9*16

// ---------------- device scratch (static; no allocation allowed) -----------
__device__ float g_E[(size_t)NMAX * KT];   // exp(sim/T), 128 MB
__device__ __align__(16) float g_pnT[DD * PSS];  // transposed+swizzled protos
__device__ float g_gated[MM * DD];         // GLU(globalPrototypes) table
__device__ float g_invn[NMAX];             // 1/||x_i||
__device__ float g_cs1[KT], g_cs2[KT], g_cs3[KT];  // column sums per iteration
__device__ int   g_lastIdx[MM];            // last row assigned to each local proto

// packed f32x2 FMA: d.lo += a.lo*b.lo ; d.hi += a.hi*b.hi  (sm_103a FFMA2)
__device__ __forceinline__ void ffma2(unsigned long long& d,
                                      unsigned long long a,
                                      unsigned long long b) {
    asm("fma.rn.f32x2 %0, %1, %2, %0;" : "+l"(d) : "l"(a), "l"(b));
}
__device__ __forceinline__ unsigned long long dup2(float a) {
    unsigned long long r;
    asm("mov.b64 %0, {%1, %1};" : "=l"(r) : "f"(a));
    return r;
}
__device__ __forceinline__ void unpack2(unsigned long long v, float& lo, float& hi) {
    asm("mov.b64 {%0, %1}, %2;" : "=f"(lo), "=f"(hi) : "l"(v));
}
__device__ __forceinline__ unsigned long long pack2(float lo, float hi) {
    unsigned long long r;
    asm("mov.b64 %0, {%1, %2};" : "=l"(r) : "f"(lo), "f"(hi));
    return r;
}

// cp.async 16B chunk
__device__ __forceinline__ void cpa16(uint32_t saddr, const void* gaddr) {
    asm volatile("cp.async.cg.shared.global [%0], [%1], 16;"
                 :: "r"(saddr), "l"(gaddr));
}
__device__ __forceinline__ void cpa_commit() {
    asm volatile("cp.async.commit_group;");
}
template<int N>
__device__ __forceinline__ void cpa_wait() {
    asm volatile("cp.async.wait_group %0;" :: "n"(N));
}

// ---------------- setup: proto normalize(+transpose) + GLU table + resets --
__global__ void k_setup(const float* __restrict__ localP,
                        const float* __restrict__ globalP,
                        const float* __restrict__ W,
                        const float* __restrict__ bias) {
    int b = blockIdx.x;
    int t = threadIdx.x;           // 384 threads
    if (b < KT) {
        const float* src = (b < MM) ? (localP + b * DD) : (globalP + (b - MM) * DD);
        float v = (t < DD) ? src[t] : 0.0f;
        float ss = v * v;
        #pragma unroll
        for (int o = 16; o; o >>= 1) ss += __shfl_xor_sync(0xffffffffu, ss, o);
        __shared__ float tot;
        if (t == 0) tot = 0.0f;
        __syncthreads();
        if ((t & 31) == 0) atomicAdd(&tot, ss);
        __syncthreads();
        float rinv = rsqrtf(fmaxf(tot, 1e-12f));
        // transposed, bank-swizzled store: row=k, col = b + 2*(b>>4)
        if (t < DD) g_pnT[t * PSS + b + ((b >> 4) << 1)] = v * rinv;
    } else if (b < KT + MM) {
        // GLU table row m: lin = G[m] @ W + b ; gated = lin[:D]*sigmoid(lin[D:])
        int m = b - KT;
        __shared__ float gp[DD];
        __shared__ float lin[2 * DD];
        if (t < DD) gp[t] = globalP[m * DD + t];
        __syncthreads();
        float acc = bias[t];
        for (int k = 0; k < DD; k++) acc += gp[k] * W[k * (2 * DD) + t];
        lin[t] = acc;
        __syncthreads();
        if (t < DD) {
            float z = lin[t + DD];
            float sig = 1.0f / (1.0f + __expf(-z));
            g_gated[m * DD + t] = lin[t] * sig;
        }
    } else {
        // resets (must re-run on every graph replay)
        if (t < KT) { g_cs1[t] = 0.0f; g_cs2[t] = 0.0f; g_cs3[t] = 0.0f; }
        if (t < MM) g_lastIdx[t] = -1;
    }
}

// ---------------- row inverse norms of x -----------------------------------
__global__ void k_rownorm(const float* __restrict__ x, int n) {
    int lane = threadIdx.x & 31;
    int warp = (blockIdx.x * blockDim.x + threadIdx.x) >> 5;
    int nw   = (gridDim.x * blockDim.x) >> 5;
    for (int row = warp; row < n; row += nw) {
        const float* xr = x + (size_t)row * DD;
        float ss = 0.0f;
        #pragma unroll
        for (int k = 0; k < 6; k++) { float v = xr[lane + 32 * k]; ss += v * v; }
        #pragma unroll
        for (int o = 16; o; o >>= 1) ss += __shfl_xor_sync(0xffffffffu, ss, o);
        if (lane == 0) g_invn[row] = rsqrtf(fmaxf(ss, 1e-12f));
    }
}

// ---------------- GEMM: E = exp(sim/T), row factor a1, colsum1 -------------
// C tile 128x256, 256 threads, thread tile 8 rows x 16 cols, FFMA2 core.
// 8x16 tile: per warp-kk 8 A-broadcast LDS.32 + 8 LDS.64 = 24 crossbar cyc
// for 64 FFMA2 -> SM crossbar (192 cyc/kk) below FMA pipe (256 cyc/kk):
// FMA-pipe-bound. Both tiles double-buffered via cp.async; ps stages are
// contiguous copies from the pre-transposed+swizzled g_pnT.
__global__ __launch_bounds__(256, 1)
void k_gemm(const float* __restrict__ x, int n) {
    __shared__ __align__(16) float xs[2][BR * XSP];     // 2 x 18.4 KB
    __shared__ __align__(16) float ps[2][KC * PSS];     // 2 x 36.9 KB
    __shared__ float a_s[BR];

    int tid = threadIdx.x;
    int tr = tid >> 4;                    // 0..15 row group (8 rows each)
    int tc = tid & 15;                    // 0..15 col group
    int r0 = blockIdx.x * BR;

    unsigned long long acc2[8][8];        // packed f32x2 accumulators (8x16)
    #pragma unroll
    for (int i = 0; i < 8; i++)
        #pragma unroll
        for (int j = 0; j < 8; j++) acc2[i][j] = 0ull;

    uint32_t xs_sb[2], ps_sb[2];
    #pragma unroll
    for (int bfi = 0; bfi < 2; bfi++) {
        xs_sb[bfi] = (uint32_t)__cvta_generic_to_shared(&xs[bfi][0]);
        ps_sb[bfi] = (uint32_t)__cvta_generic_to_shared(&ps[bfi][0]);
    }

    auto issue_stage = [&](int s) {
        int k0 = s * KC;
        int bfi = s & 1;
        // xs: 128 rows x 32 floats = 1024 chunks of 16B, 4 per thread
        #pragma unroll
        for (int i = 0; i < 4; i++) {
            int ch = tid + i * 256;
            int r = ch >> 3, kc = ch & 7;
            cpa16(xs_sb[bfi] + (uint32_t)(r * XSP + kc * 4) * 4,
                  x + (size_t)(r0 + r) * DD + k0 + kc * 4);
        }
        // ps: one contiguous 32*PSS-float block from g_pnT (2304 chunks)
        const float* src = g_pnT + (size_t)k0 * PSS;
        #pragma unroll
        for (int i = 0; i < 9; i++) {
            int ch = tid + i * 256;
            cpa16(ps_sb[bfi] + (uint32_t)ch * 16, src + ch * 4);
        }
        cpa_commit();
    };

    issue_stage(0);

    for (int s = 0; s < NSTG; s++) {
        if (s + 1 < NSTG) { issue_stage(s + 1); cpa_wait<1>(); }
        else              { cpa_wait<0>(); }
        __syncthreads();

        const float* xb = &xs[s & 1][0];
        const float* pb = &ps[s & 1][0];
        #pragma unroll
        for (int kk = 0; kk < KC; kk++) {
            unsigned long long av[8];
            #pragma unroll
            for (int i = 0; i < 8; i++) av[i] = dup2(xb[(tr * 8 + i) * XSP + kk]);
            const unsigned long long* bp =
                (const unsigned long long*)&pb[kk * PSS + tc * 18];  // swizzled base
            #pragma unroll
            for (int j = 0; j < 8; j++) {
                unsigned long long b = bp[j];
                #pragma unroll
                for (int i = 0; i < 8; i++) ffma2(acc2[i][j], av[i], b);
            }
        }
        __syncthreads();
    }

    // epilogue: normalize row, exponentiate, rowsum; store E; repack exps
    float rsum[8];
    float sc[8];
    #pragma unroll
    for (int i = 0; i < 8; i++) {
        sc[i] = g_invn[r0 + tr * 8 + i] * TINV;
        rsum[i] = 0.0f;
    }
    #pragma unroll
    for (int i = 0; i < 8; i++) {
        float4* dst = (float4*)(g_E + (size_t)(r0 + tr * 8 + i) * KT + tc * 16);
        #pragma unroll
        for (int j2 = 0; j2 < 4; j2++) {
            float l0, h0, l1, h1;
            unpack2(acc2[i][2 * j2],     l0, h0);
            unpack2(acc2[i][2 * j2 + 1], l1, h1);
            float e0 = __expf(l0 * sc[i]);
            float e1 = __expf(h0 * sc[i]);
            float e2 = __expf(l1 * sc[i]);
            float e3 = __expf(h1 * sc[i]);
            rsum[i] += (e0 + e1) + (e2 + e3);
            acc2[i][2 * j2]     = pack2(e0, e1);
            acc2[i][2 * j2 + 1] = pack2(e2, e3);
            dst[j2] = make_float4(e0, e1, e2, e3);
        }
    }

    // a1_i = 1/(n * rowsum_i)   (red overlays xs — dead after the k loop)
    float (*red)[17] = (float (*)[17])&xs[0][0];
    #pragma unroll
    for (int i = 0; i < 8; i++) red[tr * 8 + i][tc] = rsum[i];
    __syncthreads();
    if (tid < BR) {
        float s = 0.0f;
        #pragma unroll
        for (int j = 0; j < 16; j++) s += red[tid][j];
        a_s[tid] = 1.0f / ((float)n * s);
    }
    __syncthreads();

    // colsum1_j += sum_rows a1_i * E_ij   (block-local reduce, one atomic/col)
    float* cred = &ps[0][0];              // reuse ps smem as [16][256]
    #pragma unroll
    for (int j = 0; j < 8; j++) {
        float s0 = 0.0f, s1 = 0.0f;
        #pragma unroll
        for (int i = 0; i < 8; i++) {
            float lo, hi;
            unpack2(acc2[i][j], lo, hi);
            float a = a_s[tr * 8 + i];
            s0 += a * lo;
            s1 += a * hi;
        }
        cred[tr * 256 + tc * 16 + 2 * j]     = s0;
        cred[tr * 256 + tc * 16 + 2 * j + 1] = s1;
    }
    __syncthreads();
    {
        int c = tid;                      // 256 threads, 256 cols
        float s = 0.0f;
        #pragma unroll
        for (int g = 0; g < 16; g++) s += cred[g * 256 + c];
        atomicAdd(&g_cs1[c], s);
    }
}

// ---------------- sinkhorn pass: b from cs_in; a per-row; accumulate cs_out
// 4 rows per warp iteration: 8 LDG.128 in flight before the reduce chains.
template<int P>
__global__ void k_pass(int n) {
    const float* csin  = (P == 1) ? g_cs1 : g_cs2;
    float*       csout = (P == 1) ? g_cs2 : g_cs3;
    int lane = threadIdx.x & 31;
    int warp = (blockIdx.x * blockDim.x + threadIdx.x) >> 5;
    int nw   = (gridDim.x * blockDim.x) >> 5;

    float bb[8];
    #pragma unroll
    for (int j = 0; j < 8; j++) bb[j] = 1.0f / ((float)KT * csin[lane * 8 + j]);

    float cacc[8] = {0.f, 0.f, 0.f, 0.f, 0.f, 0.f, 0.f, 0.f};
    float ninv = 1.0f / (float)n;
    for (int rg = warp * 4; rg < n; rg += nw * 4) {
        float4 e[4][2];
        #pragma unroll
        for (int r = 0; r < 4; r++) {
            const float4* er = (const float4*)(g_E + (size_t)(rg + r) * KT) + lane * 2;
            e[r][0] = er[0]; e[r][1] = er[1];
        }
        #pragma unroll
        for (int r = 0; r < 4; r++) {
            float s = e[r][0].x * bb[0] + e[r][0].y * bb[1] + e[r][0].z * bb[2] + e[r][0].w * bb[3]
                    + e[r][1].x * bb[4] + e[r][1].y * bb[5] + e[r][1].z * bb[6] + e[r][1].w * bb[7];
            #pragma unroll
            for (int o = 16; o; o >>= 1) s += __shfl_xor_sync(0xffffffffu, s, o);
            float a = ninv / s;
            cacc[0] += a * e[r][0].x; cacc[1] += a * e[r][0].y;
            cacc[2] += a * e[r][0].z; cacc[3] += a * e[r][0].w;
            cacc[4] += a * e[r][1].x; cacc[5] += a * e[r][1].y;
            cacc[6] += a * e[r][1].z; cacc[7] += a * e[r][1].w;
        }
    }
    __shared__ float sacc[KT];
    if (threadIdx.x < KT) sacc[threadIdx.x] = 0.0f;
    __syncthreads();
    #pragma unroll
    for (int j = 0; j < 8; j++) atomicAdd(&sacc[lane * 8 + j], cacc[j]);
    __syncthreads();
    if (threadIdx.x < KT) atomicAdd(&csout[threadIdx.x], sacc[threadIdx.x]);
}

// ---------------- final: argmaxes, output blend+normalize, lastIdx ---------
__global__ void k_final(const float* __restrict__ x, float* __restrict__ out, int n) {
    int lane = threadIdx.x & 31;
    int warp = (blockIdx.x * blockDim.x + threadIdx.x) >> 5;
    int nw   = (gridDim.x * blockDim.x) >> 5;

    float bb[8];
    #pragma unroll
    for (int j = 0; j < 8; j++) bb[j] = 1.0f / ((float)KT * g_cs3[lane * 8 + j]);

    for (int rg = warp * 2; rg < n; rg += nw * 2) {
        float4 e[2][2];
        #pragma unroll
        for (int r = 0; r < 2; r++) {
            const float4* er = (const float4*)(g_E + (size_t)(rg + r) * KT) + lane * 2;
            e[r][0] = er[0]; e[r][1] = er[1];
        }
        #pragma unroll
        for (int r = 0; r < 2; r++) {
            int row = rg + r;
            float v[8] = { e[r][0].x * bb[0], e[r][0].y * bb[1], e[r][0].z * bb[2], e[r][0].w * bb[3],
                           e[r][1].x * bb[4], e[r][1].y * bb[5], e[r][1].z * bb[6], e[r][1].w * bb[7] };
            float best = v[0]; int bi = lane * 8;
            #pragma unroll
            for (int j = 1; j < 8; j++)
                if (v[j] > best) { best = v[j]; bi = lane * 8 + j; }
            // reduce within 16-lane halves (lanes 0..15: local cols, 16..31: global)
            #pragma unroll
            for (int o = 1; o < 16; o <<= 1) {
                float ob = __shfl_xor_sync(0xffffffffu, best, o);
                int  obi = __shfl_xor_sync(0xffffffffu, bi, o);
                if (ob > best || (ob == best && obi < bi)) { best = ob; bi = obi; }
            }
            int lidx = __shfl_sync(0xffffffffu, bi, 0);         // 0..127 (first occurrence)
            int gidx = __shfl_sync(0xffffffffu, bi, 16) - MM;   // 0..127
            if (lane == 0) atomicMax(&g_lastIdx[lidx], row);    // last-write-wins

            const float* xr = x + (size_t)row * DD;
            const float* gt = g_gated + (size_t)gidx * DD;
            float o6[6]; float ss = 0.0f;
            #pragma unroll
            for (int k = 0; k < 6; k++) {
                float ov = 0.5f * (gt[lane + 32 * k] + xr[lane + 32 * k]);
                o6[k] = ov; ss += ov * ov;
            }
            #pragma unroll
            for (int o = 16; o; o >>= 1) ss += __shfl_xor_sync(0xffffffffu, ss, o);
            float rinv = rsqrtf(fmaxf(ss, 1e-12f));
            float* orow = out + (size_t)row * DD;
            #pragma unroll
            for (int k = 0; k < 6; k++) orow[lane + 32 * k] = o6[k] * rinv;
        }
    }
}

// ---------------- EMA finalize: last-write-wins scatter --------------------
__global__ void k_ema(const float* __restrict__ x,
                      const float* __restrict__ localP,
                      float* __restrict__ outLocal) {
    int m = blockIdx.x;
    int t = threadIdx.x;   // 192
    int i = g_lastIdx[m];
    float lv = localP[m * DD + t];
    float v = (i >= 0) ? (0.96f * lv + (1.0f - 0.96f) * x[(size_t)i * DD + t]) : lv;
    outLocal[m * DD + t] = v;
}

// ---------------- launcher -------------------------------------------------
extern "C" void kernel_launch(void* const* d_in, const int* in_sizes, int n_in,
                              void* d_out, int out_size) {
    const float* proj    = (const float*)d_in[0];
    const float* localP  = (const float*)d_in[1];
    const float* globalP = (const float*)d_in[2];
    const float* W       = (const float*)d_in[3];
    const float* bias    = (const float*)d_in[4];
    float* out = (float*)d_out;

    int n = in_sizes[0] / DD;        // 131072
    float* outLocal = out + (size_t)in_sizes[0];

    k_setup<<<KT + MM + 1, 2 * DD>>>(localP, globalP, W, bias);
    k_rownorm<<<512, 256>>>(proj, n);
    k_gemm<<<n / BR, 256>>>(proj, n);
    k_pass<1><<<1024, 256>>>(n);
    k_pass<2><<<1024, 256>>>(n);
    k_final<<<1024, 256>>>(proj, out, n);
    k_ema<<<MM, DD>>>(proj, localP, outLocal);
}

// round 12
// speedup vs baseline: 1.3902x; 1.0011x over previous
#include <cuda_runtime.h>
#include <cstdint>

// Problem constants (fixed shapes for this problem instance)
#define DD     192          // projection dim
#define MM     128          // memory bank size
#define KT     256          // 2*MM prototypes
#define NMAX   131072       // 128*1024 rows
#define TINV   20.0f        // 1/temperature

#define PSS    288          // swizzled proto row stride (floats); 1152 B = 9*128
#define KC     32
#define NSTG   6            // 192 / 32
#define BR     128          // block row tile
#define XSP    36           // xs row stride (floats), 144 B = 9*16

// ---------------- device scratch (static; no allocation allowed) -----------
__device__ float g_E[(size_t)NMAX * KT];   // exp(sim/T), 128 MB
__device__ __align__(16) float g_pnT[DD * PSS];  // transposed+swizzled protos
__device__ float g_gated[MM * DD];         // GLU(globalPrototypes) table
__device__ float g_invn[NMAX];             // 1/||x_i||
__device__ float g_cs1[KT], g_cs2[KT], g_cs3[KT];  // column sums per iteration
__device__ int   g_lastIdx[MM];            // last row assigned to each local proto

// packed f32x2 FMA: d.lo += a.lo*b.lo ; d.hi += a.hi*b.hi  (sm_103a FFMA2)
__device__ __forceinline__ void ffma2(unsigned long long& d,
                                      unsigned long long a,
                                      unsigned long long b) {
    asm("fma.rn.f32x2 %0, %1, %2, %0;" : "+l"(d) : "l"(a), "l"(b));
}
__device__ __forceinline__ unsigned long long dup2(float a) {
    unsigned long long r;
    asm("mov.b64 %0, {%1, %1};" : "=l"(r) : "f"(a));
    return r;
}
__device__ __forceinline__ void unpack2(unsigned long long v, float& lo, float& hi) {
    asm("mov.b64 {%0, %1}, %2;" : "=f"(lo), "=f"(hi) : "l"(v));
}
__device__ __forceinline__ unsigned long long pack2(float lo, float hi) {
    unsigned long long r;
    asm("mov.b64 %0, {%1, %2};" : "=l"(r) : "f"(lo), "f"(hi));
    return r;
}

// cp.async 16B chunk
__device__ __forceinline__ void cpa16(uint32_t saddr, const void* gaddr) {
    asm volatile("cp.async.cg.shared.global [%0], [%1], 16;"
                 :: "r"(saddr), "l"(gaddr));
}
__device__ __forceinline__ void cpa_commit() {
    asm volatile("cp.async.commit_group;");
}
template<int N>
__device__ __forceinline__ void cpa_wait() {
    asm volatile("cp.async.wait_group %0;" :: "n"(N));
}

// ---------------- setup: proto normalize(+transpose) + GLU table + resets --
__global__ void k_setup(const float* __restrict__ localP,
                        const float* __restrict__ globalP,
                        const float* __restrict__ W,
                        const float* __restrict__ bias) {
    int b = blockIdx.x;
    int t = threadIdx.x;           // 384 threads
    if (b < KT) {
        const float* src = (b < MM) ? (localP + b * DD) : (globalP + (b - MM) * DD);
        float v = (t < DD) ? src[t] : 0.0f;
        float ss = v * v;
        #pragma unroll
        for (int o = 16; o; o >>= 1) ss += __shfl_xor_sync(0xffffffffu, ss, o);
        __shared__ float tot;
        if (t == 0) tot = 0.0f;
        __syncthreads();
        if ((t & 31) == 0) atomicAdd(&tot, ss);
        __syncthreads();
        float rinv = rsqrtf(fmaxf(tot, 1e-12f));
        // transposed, bank-swizzled store: row=k, col = b + 2*(b>>4)
        if (t < DD) g_pnT[t * PSS + b + ((b >> 4) << 1)] = v * rinv;
    } else if (b < KT + MM) {
        // GLU table row m: lin = G[m] @ W + b ; gated = lin[:D]*sigmoid(lin[D:])
        int m = b - KT;
        __shared__ float gp[DD];
        __shared__ float lin[2 * DD];
        if (t < DD) gp[t] = globalP[m * DD + t];
        __syncthreads();
        float acc = bias[t];
        for (int k = 0; k < DD; k++) acc += gp[k] * W[k * (2 * DD) + t];
        lin[t] = acc;
        __syncthreads();
        if (t < DD) {
            float z = lin[t + DD];
            float sig = 1.0f / (1.0f + __expf(-z));
            g_gated[m * DD + t] = lin[t] * sig;
        }
    } else {
        // resets (must re-run on every graph replay)
        if (t < KT) { g_cs1[t] = 0.0f; g_cs2[t] = 0.0f; g_cs3[t] = 0.0f; }
        if (t < MM) g_lastIdx[t] = -1;
    }
}

// ---------------- row inverse norms of x -----------------------------------
__global__ void k_rownorm(const float* __restrict__ x, int n) {
    int lane = threadIdx.x & 31;
    int warp = (blockIdx.x * blockDim.x + threadIdx.x) >> 5;
    int nw   = (gridDim.x * blockDim.x) >> 5;
    for (int row = warp; row < n; row += nw) {
        const float* xr = x + (size_t)row * DD;
        float ss = 0.0f;
        #pragma unroll
        for (int k = 0; k < 6; k++) { float v = xr[lane + 32 * k]; ss += v * v; }
        #pragma unroll
        for (int o = 16; o; o >>= 1) ss += __shfl_xor_sync(0xffffffffu, ss, o);
        if (lane == 0) g_invn[row] = rsqrtf(fmaxf(ss, 1e-12f));
    }
}

// ---------------- GEMM: E = exp(sim/T), row factor a1, colsum1 -------------
// C tile 128x256, 256 threads, thread tile 8 rows x 16 cols, FFMA2 core.
// 8x16 tile: per warp-kk 8 A-broadcast LDS.32 + 8 LDS.64 = 24 crossbar cyc
// for 64 FFMA2 -> SM crossbar (192 cyc/kk) below FMA pipe (256 cyc/kk):
// FMA-pipe-bound. Both tiles double-buffered via cp.async; ps stages are
// contiguous copies from the pre-transposed+swizzled g_pnT.
__global__ __launch_bounds__(256, 1)
void k_gemm(const float* __restrict__ x, int n) {
    __shared__ __align__(16) float xs[2][BR * XSP];     // 2 x 18.4 KB
    __shared__ __align__(16) float ps[2][KC * PSS];     // 2 x 36.9 KB
    __shared__ float a_s[BR];

    int tid = threadIdx.x;
    int tr = tid >> 4;                    // 0..15 row group (8 rows each)
    int tc = tid & 15;                    // 0..15 col group
    int r0 = blockIdx.x * BR;

    unsigned long long acc2[8][8];        // packed f32x2 accumulators (8x16)
    #pragma unroll
    for (int i = 0; i < 8; i++)
        #pragma unroll
        for (int j = 0; j < 8; j++) acc2[i][j] = 0ull;

    uint32_t xs_sb[2], ps_sb[2];
    #pragma unroll
    for (int bfi = 0; bfi < 2; bfi++) {
        xs_sb[bfi] = (uint32_t)__cvta_generic_to_shared(&xs[bfi][0]);
        ps_sb[bfi] = (uint32_t)__cvta_generic_to_shared(&ps[bfi][0]);
    }

    auto issue_stage = [&](int s) {
        int k0 = s * KC;
        int bfi = s & 1;
        // xs: 128 rows x 32 floats = 1024 chunks of 16B, 4 per thread
        #pragma unroll
        for (int i = 0; i < 4; i++) {
            int ch = tid + i * 256;
            int r = ch >> 3, kc = ch & 7;
            cpa16(xs_sb[bfi] + (uint32_t)(r * XSP + kc * 4) * 4,
                  x + (size_t)(r0 + r) * DD + k0 + kc * 4);
        }
        // ps: one contiguous 32*PSS-float block from g_pnT (2304 chunks)
        const float* src = g_pnT + (size_t)k0 * PSS;
        #pragma unroll
        for (int i = 0; i < 9; i++) {
            int ch = tid + i * 256;
            cpa16(ps_sb[bfi] + (uint32_t)ch * 16, src + ch * 4);
        }
        cpa_commit();
    };

    issue_stage(0);

    for (int s = 0; s < NSTG; s++) {
        if (s + 1 < NSTG) { issue_stage(s + 1); cpa_wait<1>(); }
        else              { cpa_wait<0>(); }
        __syncthreads();

        const float* xb = &xs[s & 1][0];
        const float* pb = &ps[s & 1][0];
        #pragma unroll
        for (int kk = 0; kk < KC; kk++) {
            unsigned long long av[8];
            #pragma unroll
            for (int i = 0; i < 8; i++) av[i] = dup2(xb[(tr * 8 + i) * XSP + kk]);
            const unsigned long long* bp =
                (const unsigned long long*)&pb[kk * PSS + tc * 18];  // swizzled base
            #pragma unroll
            for (int j = 0; j < 8; j++) {
                unsigned long long b = bp[j];
                #pragma unroll
                for (int i = 0; i < 8; i++) ffma2(acc2[i][j], av[i], b);
            }
        }
        __syncthreads();
    }

    // epilogue: normalize row, exponentiate, rowsum; store E; repack exps
    float rsum[8];
    float sc[8];
    #pragma unroll
    for (int i = 0; i < 8; i++) {
        sc[i] = g_invn[r0 + tr * 8 + i] * TINV;
        rsum[i] = 0.0f;
    }
    #pragma unroll
    for (int i = 0; i < 8; i++) {
        float4* dst = (float4*)(g_E + (size_t)(r0 + tr * 8 + i) * KT + tc * 16);
        #pragma unroll
        for (int j2 = 0; j2 < 4; j2++) {
            float l0, h0, l1, h1;
            unpack2(acc2[i][2 * j2],     l0, h0);
            unpack2(acc2[i][2 * j2 + 1], l1, h1);
            float e0 = __expf(l0 * sc[i]);
            float e1 = __expf(h0 * sc[i]);
            float e2 = __expf(l1 * sc[i]);
            float e3 = __expf(h1 * sc[i]);
            rsum[i] += (e0 + e1) + (e2 + e3);
            acc2[i][2 * j2]     = pack2(e0, e1);
            acc2[i][2 * j2 + 1] = pack2(e2, e3);
            dst[j2] = make_float4(e0, e1, e2, e3);
        }
    }

    // a1_i = 1/(n * rowsum_i)   (red overlays xs — dead after the k loop)
    float (*red)[17] = (float (*)[17])&xs[0][0];
    #pragma unroll
    for (int i = 0; i < 8; i++) red[tr * 8 + i][tc] = rsum[i];
    __syncthreads();
    if (tid < BR) {
        float s = 0.0f;
        #pragma unroll
        for (int j = 0; j < 16; j++) s += red[tid][j];
        a_s[tid] = 1.0f / ((float)n * s);
    }
    __syncthreads();

    // colsum1_j += sum_rows a1_i * E_ij   (block-local reduce, one atomic/col)
    float* cred = &ps[0][0];              // reuse ps smem as [16][256]
    #pragma unroll
    for (int j = 0; j < 8; j++) {
        float s0 = 0.0f, s1 = 0.0f;
        #pragma unroll
        for (int i = 0; i < 8; i++) {
            float lo, hi;
            unpack2(acc2[i][j], lo, hi);
            float a = a_s[tr * 8 + i];
            s0 += a * lo;
            s1 += a * hi;
        }
        cred[tr * 256 + tc * 16 + 2 * j]     = s0;
        cred[tr * 256 + tc * 16 + 2 * j + 1] = s1;
    }
    __syncthreads();
    {
        int c = tid;                      // 256 threads, 256 cols
        float s = 0.0f;
        #pragma unroll
        for (int g = 0; g < 16; g++) s += cred[g * 256 + c];
        atomicAdd(&g_cs1[c], s);
    }
}

// ---------------- sinkhorn pass: b from cs_in; a per-row; accumulate cs_out
// 4 rows per warp iteration: 8 LDG.128 in flight before the reduce chains.
template<int P>
__global__ void k_pass(int n) {
    const float* csin  = (P == 1) ? g_cs1 : g_cs2;
    float*       csout = (P == 1) ? g_cs2 : g_cs3;
    int lane = threadIdx.x & 31;
    int warp = (blockIdx.x * blockDim.x + threadIdx.x) >> 5;
    int nw   = (gridDim.x * blockDim.x) >> 5;

    float bb[8];
    #pragma unroll
    for (int j = 0; j < 8; j++) bb[j] = 1.0f / ((float)KT * csin[lane * 8 + j]);

    float cacc[8] = {0.f, 0.f, 0.f, 0.f, 0.f, 0.f, 0.f, 0.f};
    float ninv = 1.0f / (float)n;
    for (int rg = warp * 4; rg < n; rg += nw * 4) {
        float4 e[4][2];
        #pragma unroll
        for (int r = 0; r < 4; r++) {
            const float4* er = (const float4*)(g_E + (size_t)(rg + r) * KT) + lane * 2;
            e[r][0] = er[0]; e[r][1] = er[1];
        }
        #pragma unroll
        for (int r = 0; r < 4; r++) {
            float s = e[r][0].x * bb[0] + e[r][0].y * bb[1] + e[r][0].z * bb[2] + e[r][0].w * bb[3]
                    + e[r][1].x * bb[4] + e[r][1].y * bb[5] + e[r][1].z * bb[6] + e[r][1].w * bb[7];
            #pragma unroll
            for (int o = 16; o; o >>= 1) s += __shfl_xor_sync(0xffffffffu, s, o);
            float a = ninv / s;
            cacc[0] += a * e[r][0].x; cacc[1] += a * e[r][0].y;
            cacc[2] += a * e[r][0].z; cacc[3] += a * e[r][0].w;
            cacc[4] += a * e[r][1].x; cacc[5] += a * e[r][1].y;
            cacc[6] += a * e[r][1].z; cacc[7] += a * e[r][1].w;
        }
    }
    __shared__ float sacc[KT];
    if (threadIdx.x < KT) sacc[threadIdx.x] = 0.0f;
    __syncthreads();
    #pragma unroll
    for (int j = 0; j < 8; j++) atomicAdd(&sacc[lane * 8 + j], cacc[j]);
    __syncthreads();
    if (threadIdx.x < KT) atomicAdd(&csout[threadIdx.x], sacc[threadIdx.x]);
}

// ---------------- final: argmaxes, output blend+normalize, lastIdx ---------
__global__ void k_final(const float* __restrict__ x, float* __restrict__ out, int n) {
    int lane = threadIdx.x & 31;
    int warp = (blockIdx.x * blockDim.x + threadIdx.x) >> 5;
    int nw   = (gridDim.x * blockDim.x) >> 5;

    float bb[8];
    #pragma unroll
    for (int j = 0; j < 8; j++) bb[j] = 1.0f / ((float)KT * g_cs3[lane * 8 + j]);

    for (int rg = warp * 2; rg < n; rg += nw * 2) {
        float4 e[2][2];
        #pragma unroll
        for (int r = 0; r < 2; r++) {
            const float4* er = (const float4*)(g_E + (size_t)(rg + r) * KT) + lane * 2;
            e[r][0] = er[0]; e[r][1] = er[1];
        }
        #pragma unroll
        for (int r = 0; r < 2; r++) {
            int row = rg + r;
            float v[8] = { e[r][0].x * bb[0], e[r][0].y * bb[1], e[r][0].z * bb[2], e[r][0].w * bb[3],
                           e[r][1].x * bb[4], e[r][1].y * bb[5], e[r][1].z * bb[6], e[r][1].w * bb[7] };
            float best = v[0]; int bi = lane * 8;
            #pragma unroll
            for (int j = 1; j < 8; j++)
                if (v[j] > best) { best = v[j]; bi = lane * 8 + j; }
            // reduce within 16-lane halves (lanes 0..15: local cols, 16..31: global)
            #pragma unroll
            for (int o = 1; o < 16; o <<= 1) {
                float ob = __shfl_xor_sync(0xffffffffu, best, o);
                int  obi = __shfl_xor_sync(0xffffffffu, bi, o);
                if (ob > best || (ob == best && obi < bi)) { best = ob; bi = obi; }
            }
            int lidx = __shfl_sync(0xffffffffu, bi, 0);         // 0..127 (first occurrence)
            int gidx = __shfl_sync(0xffffffffu, bi, 16) - MM;   // 0..127
            if (lane == 0) atomicMax(&g_lastIdx[lidx], row);    // last-write-wins

            const float* xr = x + (size_t)row * DD;
            const float* gt = g_gated + (size_t)gidx * DD;
            float o6[6]; float ss = 0.0f;
            #pragma unroll
            for (int k = 0; k < 6; k++) {
                float ov = 0.5f * (gt[lane + 32 * k] + xr[lane + 32 * k]);
                o6[k] = ov; ss += ov * ov;
            }
            #pragma unroll
            for (int o = 16; o; o >>= 1) ss += __shfl_xor_sync(0xffffffffu, ss, o);
            float rinv = rsqrtf(fmaxf(ss, 1e-12f));
            float* orow = out + (size_t)row * DD;
            #pragma unroll
            for (int k = 0; k < 6; k++) orow[lane + 32 * k] = o6[k] * rinv;
        }
    }
}

// ---------------- EMA finalize: last-write-wins scatter --------------------
__global__ void k_ema(const float* __restrict__ x,
                      const float* __restrict__ localP,
                      float* __restrict__ outLocal) {
    int m = blockIdx.x;
    int t = threadIdx.x;   // 192
    int i = g_lastIdx[m];
    float lv = localP[m * DD + t];
    float v = (i >= 0) ? (0.96f * lv + (1.0f - 0.96f) * x[(size_t)i * DD + t]) : lv;
    outLocal[m * DD + t] = v;
}

// ---------------- launcher -------------------------------------------------
extern "C" void kernel_launch(void* const* d_in, const int* in_sizes, int n_in,
                              void* d_out, int out_size) {
    const float* proj    = (const float*)d_in[0];
    const float* localP  = (const float*)d_in[1];
    const float* globalP = (const float*)d_in[2];
    const float* W       = (const float*)d_in[3];
    const float* bias    = (const float*)d_in[4];
    float* out = (float*)d_out;

    int n = in_sizes[0] / DD;        // 131072
    float* outLocal = out + (size_t)in_sizes[0];

    k_setup<<<KT + MM + 1, 2 * DD>>>(localP, globalP, W, bias);
    k_rownorm<<<512, 256>>>(proj, n);
    k_gemm<<<n / BR, 256>>>(proj, n);
    k_pass<1><<<1024, 256>>>(n);
    k_pass<2><<<1024, 256>>>(n);
    k_final<<<1024, 256>>>(proj, out, n);
    k_ema<<<MM, DD>>>(proj, localP, outLocal);
}

// round 14
// speedup vs baseline: 1.4364x; 1.0332x over previous
#include <cuda_runtime.h>
#include <cuda_bf16.h>
#include <cstdint>

#define DD 192
#define MM 128
#define KT 256
#define TINV 20.0f
#define BR 128
#define KCH 64
#define NCH 3
#define SK 72                      // tile k-stride in bf16 (conflict-free: bank=lane)

__device__ float g_E[(size_t)131072 * KT];
__device__ __align__(16) __nv_bfloat16 g_pB[NCH][3][KT * SK]; // padded B split images
__device__ float g_gated[MM * DD];
__device__ float g_invn[131072];
__device__ float g_cs1[KT], g_cs2[KT], g_cs3[KT];
__device__ int g_lastIdx[MM];

__device__ __forceinline__ void cpa16(uint32_t s, const void* g) {
    asm volatile("cp.async.cg.shared.global [%0], [%1], 16;" :: "r"(s), "l"(g));
}
__device__ __forceinline__ void cpacm() { asm volatile("cp.async.commit_group;"); }
template<int N> __device__ __forceinline__ void cpaw() {
    asm volatile("cp.async.wait_group %0;" :: "n"(N));
}
__device__ __forceinline__ void mma16816(float* d, const uint32_t* a, const uint32_t* b) {
    asm volatile("mma.sync.aligned.m16n8k16.row.col.f32.bf16.bf16.f32 "
        "{%0,%1,%2,%3}, {%4,%5,%6,%7}, {%8,%9}, {%0,%1,%2,%3};"
        : "+f"(d[0]), "+f"(d[1]), "+f"(d[2]), "+f"(d[3])
        : "r"(a[0]), "r"(a[1]), "r"(a[2]), "r"(a[3]), "r"(b[0]), "r"(b[1]));
}
__device__ __forceinline__ void split3(float v, uint16_t& h, uint16_t& m, uint16_t& l) {
    __nv_bfloat16 bh = __float2bfloat16_rn(v); float r1 = v - __bfloat162float(bh);
    __nv_bfloat16 bm = __float2bfloat16_rn(r1); float r2 = r1 - __bfloat162float(bm);
    __nv_bfloat16 bl = __float2bfloat16_rn(r2);
    h = __bfloat16_as_ushort(bh); m = __bfloat16_as_ushort(bm); l = __bfloat16_as_ushort(bl);
}

__global__ void k_setup(const float* __restrict__ localP, const float* __restrict__ globalP,
                        const float* __restrict__ W, const float* __restrict__ bias) {
    int b = blockIdx.x, t = threadIdx.x;  // 384 thr
    if (b < KT) {
        const float* src = (b < MM) ? (localP + b * DD) : (globalP + (b - MM) * DD);
        float v = (t < DD) ? src[t] : 0.0f; float ss = v * v;
        #pragma unroll
        for (int o = 16; o; o >>= 1) ss += __shfl_xor_sync(0xffffffffu, ss, o);
        __shared__ float tot; if (t == 0) tot = 0.0f; __syncthreads();
        if ((t & 31) == 0) atomicAdd(&tot, ss); __syncthreads();
        float rinv = rsqrtf(fmaxf(tot, 1e-12f));
        if (t < DD) {
            uint16_t h, m, l; split3(v * rinv, h, m, l);
            int ch = t / KCH, kk = t % KCH;
            g_pB[ch][0][b * SK + kk] = __ushort_as_bfloat16(h);
            g_pB[ch][1][b * SK + kk] = __ushort_as_bfloat16(m);
            g_pB[ch][2][b * SK + kk] = __ushort_as_bfloat16(l);
        }
    } else if (b < KT + MM) {
        int m = b - KT; __shared__ float gp[DD]; __shared__ float lin[2 * DD];
        if (t < DD) gp[t] = globalP[m * DD + t]; __syncthreads();
        float acc = bias[t];
        for (int k = 0; k < DD; k++) acc += gp[k] * W[k * (2 * DD) + t];
        lin[t] = acc; __syncthreads();
        if (t < DD) { float z = lin[t + DD]; g_gated[m * DD + t] = lin[t] * (1.0f / (1.0f + __expf(-z))); }
    } else {
        if (t < KT) { g_cs1[t] = 0.0f; g_cs2[t] = 0.0f; g_cs3[t] = 0.0f; }
        if (t < MM) g_lastIdx[t] = -1;
    }
}

__global__ void k_rownorm(const float* __restrict__ x, int n) {
    int lane = threadIdx.x & 31, warp = (blockIdx.x * blockDim.x + threadIdx.x) >> 5, nw = (gridDim.x * blockDim.x) >> 5;
    for (int row = warp; row < n; row += nw) {
        const float* xr = x + (size_t)row * DD; float ss = 0.0f;
        #pragma unroll
        for (int k = 0; k < 6; k++) { float v = xr[lane + 32 * k]; ss += v * v; }
        #pragma unroll
        for (int o = 16; o; o >>= 1) ss += __shfl_xor_sync(0xffffffffu, ss, o);
        if (lane == 0) g_invn[row] = rsqrtf(fmaxf(ss, 1e-12f));
    }
}

// ---- tensor GEMM: per CTA 128x256x192, 6-term split-bf16 via mma.sync -----
#define A_BY (BR * SK * 2)         // 18432
#define B_BY (KT * SK * 2)         // 36864
#define SM_A 0
#define SM_B (3 * A_BY)            // 55296
#define STG_S 260
#define SM_RS 133120
#define SM_AS 133632
#define SM_CS 134144
#define SMEMTOT (SM_B + 3 * B_BY)  // 165888

__global__ __launch_bounds__(256, 1) void k_tc(const float* __restrict__ x, int n) {
    extern __shared__ char smem[];
    uint32_t sb = (uint32_t)__cvta_generic_to_shared(smem);
    int tid = threadIdx.x, r0 = blockIdx.x * BR;
    int w = tid >> 5, lane = tid & 31;
    int wm = w >> 2, wn = w & 3;          // warp grid 2(M) x 4(N), warp tile 64x64
    int g = lane >> 2, q = lane & 3;

    float d[4][8][4];                      // [mt][nt][frag] = 128 fp32
    #pragma unroll
    for (int i = 0; i < 4; i++)
        #pragma unroll
        for (int j = 0; j < 8; j++)
            #pragma unroll
            for (int k = 0; k < 4; k++) d[i][j][k] = 0.0f;

    const int nb_for_a[3] = {3, 2, 1};     // pa0:{b0,b1,b2} pa1:{b0,b1} pa2:{b0}

    for (int ch = 0; ch < NCH; ch++) {
        #pragma unroll
        for (int t3 = 0; t3 < 3; t3++) {   // B splits: contiguous cp.async
            const char* src = (const char*)&g_pB[ch][t3][0];
            #pragma unroll
            for (int i = 0; i < 9; i++) {
                int idx = tid + i * 256;   // 2304 chunks of 16B
                cpa16(sb + SM_B + t3 * B_BY + idx * 16, src + idx * 16);
            }
        }
        cpacm();
        {   // A splits: load x fp32, 3-way split, STS
            int row = tid >> 1, kb = (tid & 1) * 32;
            const float4* xs = (const float4*)(x + (size_t)(r0 + row) * DD + ch * KCH + kb);
            #pragma unroll
            for (int p = 0; p < 8; p++) {
                float4 v = xs[p];
                uint16_t h0, m0, l0, h1, m1, l1;
                int o0 = (row * SK + kb + p * 4) * 2, o1 = o0 + 4;
                split3(v.x, h0, m0, l0); split3(v.y, h1, m1, l1);
                *(uint32_t*)(smem + SM_A + 0 * A_BY + o0) = ((uint32_t)h1 << 16) | h0;
                *(uint32_t*)(smem + SM_A + 1 * A_BY + o0) = ((uint32_t)m1 << 16) | m0;
                *(uint32_t*)(smem + SM_A + 2 * A_BY + o0) = ((uint32_t)l1 << 16) | l0;
                split3(v.z, h0, m0, l0); split3(v.w, h1, m1, l1);
                *(uint32_t*)(smem + SM_A + 0 * A_BY + o1) = ((uint32_t)h1 << 16) | h0;
                *(uint32_t*)(smem + SM_A + 1 * A_BY + o1) = ((uint32_t)m1 << 16) | m0;
                *(uint32_t*)(smem + SM_A + 2 * A_BY + o1) = ((uint32_t)l1 << 16) | l0;
            }
        }
        cpaw<0>();
        __syncthreads();

        #pragma unroll
        for (int ks = 0; ks < 4; ks++) {
            int kc = ks * 16 + q * 2;
            #pragma unroll
            for (int ta = 0; ta < 3; ta++) {
                uint32_t af[4][4];
                const char* Ab = smem + SM_A + ta * A_BY;
                #pragma unroll
                for (int mt = 0; mt < 4; mt++) {
                    int rr = wm * 64 + mt * 16 + g;
                    af[mt][0] = *(const uint32_t*)(Ab + (rr * SK + kc) * 2);
                    af[mt][1] = *(const uint32_t*)(Ab + ((rr + 8) * SK + kc) * 2);
                    af[mt][2] = *(const uint32_t*)(Ab + (rr * SK + kc + 8) * 2);
                    af[mt][3] = *(const uint32_t*)(Ab + ((rr + 8) * SK + kc + 8) * 2);
                }
                #pragma unroll
                for (int tb = 0; tb < 3; tb++) {
                    if (tb >= nb_for_a[ta]) break;
                    uint32_t bf[8][2];
                    const char* Bb = smem + SM_B + tb * B_BY;
                    #pragma unroll
                    for (int nt = 0; nt < 8; nt++) {
                        int nn = wn * 64 + nt * 8 + g;
                        bf[nt][0] = *(const uint32_t*)(Bb + (nn * SK + kc) * 2);
                        bf[nt][1] = *(const uint32_t*)(Bb + (nn * SK + kc + 8) * 2);
                    }
                    #pragma unroll
                    for (int mt = 0; mt < 4; mt++)
                        #pragma unroll
                        for (int nt = 0; nt < 8; nt++)
                            mma16816(d[mt][nt], af[mt], bf[nt]);
                }
            }
        }
        __syncthreads();                   // tiles reused next chunk
    }

    // ---- epilogue: exp + rowsum + stage; then coalesced E store + colsum --
    float* stg = (float*)smem;             // [128][260]
    float* RS  = (float*)(smem + SM_RS);
    float* AS  = (float*)(smem + SM_AS);
    float* CS  = (float*)(smem + SM_CS);
    if (tid < 128) RS[tid] = 0.0f;
    if (tid < 256) CS[tid] = 0.0f;
    __syncthreads();

    #pragma unroll
    for (int mt = 0; mt < 4; mt++) {
        int rlo = wm * 64 + mt * 16 + g, rhi = rlo + 8;
        float slo = g_invn[r0 + rlo] * TINV, shi = g_invn[r0 + rhi] * TINV;
        float rs0 = 0.0f, rs1 = 0.0f;
        #pragma unroll
        for (int nt = 0; nt < 8; nt++) {
            int nn = wn * 64 + nt * 8 + q * 2;
            float e0 = __expf(d[mt][nt][0] * slo);
            float e1 = __expf(d[mt][nt][1] * slo);
            float e2 = __expf(d[mt][nt][2] * shi);
            float e3 = __expf(d[mt][nt][3] * shi);
            rs0 += e0 + e1; rs1 += e2 + e3;
            *(float2*)(stg + rlo * STG_S + nn) = make_float2(e0, e1);
            *(float2*)(stg + rhi * STG_S + nn) = make_float2(e2, e3);
        }
        atomicAdd(&RS[rlo], rs0); atomicAdd(&RS[rhi], rs1);
    }
    __syncthreads();
    if (tid < 128) AS[tid] = 1.0f / ((float)n * RS[tid]);
    __syncthreads();
    {
        int rr = tid >> 6, cc = (tid & 63) * 4;
        float c0 = 0, c1 = 0, c2 = 0, c3 = 0;
        #pragma unroll 4
        for (int rb = 0; rb < 32; rb++) {
            int r = rb * 4 + rr;
            float4 v = *(const float4*)(stg + r * STG_S + cc);
            *(float4*)(g_E + (size_t)(r0 + r) * KT + cc) = v;
            float a = AS[r];
            c0 += a * v.x; c1 += a * v.y; c2 += a * v.z; c3 += a * v.w;
        }
        atomicAdd(&CS[cc + 0], c0); atomicAdd(&CS[cc + 1], c1);
        atomicAdd(&CS[cc + 2], c2); atomicAdd(&CS[cc + 3], c3);
        __syncthreads();
        if (tid < KT) atomicAdd(&g_cs1[tid], CS[tid]);
    }
}

template<int P>
__global__ void k_pass(int n) {
    const float* ci = (P == 1) ? g_cs1 : g_cs2; float* co = (P == 1) ? g_cs2 : g_cs3;
    int lane = threadIdx.x & 31, warp = (blockIdx.x * blockDim.x + threadIdx.x) >> 5, nw = (gridDim.x * blockDim.x) >> 5;
    float bb[8];
    #pragma unroll
    for (int j = 0; j < 8; j++) bb[j] = 1.0f / ((float)KT * ci[lane * 8 + j]);
    float ca[8] = {0, 0, 0, 0, 0, 0, 0, 0};
    float ninv = 1.0f / (float)n;
    for (int rg = warp * 4; rg < n; rg += nw * 4) {
        float4 e[4][2];
        #pragma unroll
        for (int r = 0; r < 4; r++) {
            const float4* er = (const float4*)(g_E + (size_t)(rg + r) * KT) + lane * 2;
            e[r][0] = er[0]; e[r][1] = er[1];
        }
        #pragma unroll
        for (int r = 0; r < 4; r++) {
            float s = e[r][0].x * bb[0] + e[r][0].y * bb[1] + e[r][0].z * bb[2] + e[r][0].w * bb[3]
                    + e[r][1].x * bb[4] + e[r][1].y * bb[5] + e[r][1].z * bb[6] + e[r][1].w * bb[7];
            #pragma unroll
            for (int o = 16; o; o >>= 1) s += __shfl_xor_sync(0xffffffffu, s, o);
            float a = ninv / s;
            ca[0] += a * e[r][0].x; ca[1] += a * e[r][0].y; ca[2] += a * e[r][0].z; ca[3] += a * e[r][0].w;
            ca[4] += a * e[r][1].x; ca[5] += a * e[r][1].y; ca[6] += a * e[r][1].z; ca[7] += a * e[r][1].w;
        }
    }
    __shared__ float sa[KT];
    if (threadIdx.x < KT) sa[threadIdx.x] = 0.0f;
    __syncthreads();
    #pragma unroll
    for (int j = 0; j < 8; j++) atomicAdd(&sa[lane * 8 + j], ca[j]);
    __syncthreads();
    if (threadIdx.x < KT) atomicAdd(&co[threadIdx.x], sa[threadIdx.x]);
}

__global__ void k_final(const float* __restrict__ x, float* __restrict__ out, int n) {
    int lane = threadIdx.x & 31, warp = (blockIdx.x * blockDim.x + threadIdx.x) >> 5, nw = (gridDim.x * blockDim.x) >> 5;
    float bb[8];
    #pragma unroll
    for (int j = 0; j < 8; j++) bb[j] = 1.0f / ((float)KT * g_cs3[lane * 8 + j]);
    for (int rg = warp * 2; rg < n; rg += nw * 2) {
        float4 e[2][2];
        #pragma unroll
        for (int r = 0; r < 2; r++) {
            const float4* er = (const float4*)(g_E + (size_t)(rg + r) * KT) + lane * 2;
            e[r][0] = er[0]; e[r][1] = er[1];
        }
        #pragma unroll
        for (int r = 0; r < 2; r++) {
            int row = rg + r;
            float v[8] = { e[r][0].x * bb[0], e[r][0].y * bb[1], e[r][0].z * bb[2], e[r][0].w * bb[3],
                           e[r][1].x * bb[4], e[r][1].y * bb[5], e[r][1].z * bb[6], e[r][1].w * bb[7] };
            float best = v[0]; int bi = lane * 8;
            #pragma unroll
            for (int j = 1; j < 8; j++) if (v[j] > best) { best = v[j]; bi = lane * 8 + j; }
            #pragma unroll
            for (int o = 1; o < 16; o <<= 1) {
                float ob = __shfl_xor_sync(0xffffffffu, best, o);
                int  obi = __shfl_xor_sync(0xffffffffu, bi, o);
                if (ob > best || (ob == best && obi < bi)) { best = ob; bi = obi; }
            }
            int lidx = __shfl_sync(0xffffffffu, bi, 0);
            int gidx = __shfl_sync(0xffffffffu, bi, 16) - MM;
            if (lane == 0) atomicMax(&g_lastIdx[lidx], row);
            const float* xr = x + (size_t)row * DD;
            const float* gt = g_gated + (size_t)gidx * DD;
            float o6[6]; float ss = 0.0f;
            #pragma unroll
            for (int k = 0; k < 6; k++) { float ov = 0.5f * (gt[lane + 32 * k] + xr[lane + 32 * k]); o6[k] = ov; ss += ov * ov; }
            #pragma unroll
            for (int o = 16; o; o >>= 1) ss += __shfl_xor_sync(0xffffffffu, ss, o);
            float rinv = rsqrtf(fmaxf(ss, 1e-12f));
            float* orow = out + (size_t)row * DD;
            #pragma unroll
            for (int k = 0; k < 6; k++) orow[lane + 32 * k] = o6[k] * rinv;
        }
    }
}

__global__ void k_ema(const float* __restrict__ x, const float* __restrict__ localP,
                      float* __restrict__ outLocal) {
    int m = blockIdx.x, t = threadIdx.x;
    int i = g_lastIdx[m];
    float lv = localP[m * DD + t];
    outLocal[m * DD + t] = (i >= 0) ? (0.96f * lv + 0.04f * x[(size_t)i * DD + t]) : lv;
}

extern "C" void kernel_launch(void* const* d_in, const int* in_sizes, int n_in,
                              void* d_out, int out_size) {
    const float* proj = (const float*)d_in[0];
    const float* localP = (const float*)d_in[1];
    const float* globalP = (const float*)d_in[2];
    const float* W = (const float*)d_in[3];
    const float* bias = (const float*)d_in[4];
    float* out = (float*)d_out;
    int n = in_sizes[0] / DD;
    float* outLocal = out + (size_t)in_sizes[0];

    cudaFuncSetAttribute(k_tc, cudaFuncAttributeMaxDynamicSharedMemorySize, SMEMTOT);

    k_setup<<<KT + MM + 1, 2 * DD>>>(localP, globalP, W, bias);
    k_rownorm<<<512, 256>>>(proj, n);
    k_tc<<<n / BR, 256, SMEMTOT>>>(proj, n);
    k_pass<1><<<1024, 256>>>(n);
    k_pass<2><<<1024, 256>>>(n);
    k_final<<<1024, 256>>>(proj, out, n);
    k_ema<<<MM, DD>>>(proj, localP, outLocal);
}

// round 15
// speedup vs baseline: 1.8925x; 1.3175x over previous
#include <cuda_runtime.h>
#include <cuda_bf16.h>
#include <cstdint>

#define DD 192
#define MM 128
#define KT 256
#define TINV 20.0f
#define BR 128
#define KCH 64
#define NCH 3
#define SK 72                      // tile k-stride in bf16 (conflict-free: bank=lane)

__device__ float g_E[(size_t)131072 * KT];
__device__ __align__(16) __nv_bfloat16 g_pB[NCH][2][KT * SK]; // 2-way split B images
__device__ float g_gated[MM * DD];
__device__ float g_cs1[KT], g_cs2[KT], g_cs3[KT];
__device__ int g_lastIdx[MM];

__device__ __forceinline__ void cpa16(uint32_t s, const void* g) {
    asm volatile("cp.async.cg.shared.global [%0], [%1], 16;" :: "r"(s), "l"(g));
}
__device__ __forceinline__ void cpacm() { asm volatile("cp.async.commit_group;"); }
template<int N> __device__ __forceinline__ void cpaw() {
    asm volatile("cp.async.wait_group %0;" :: "n"(N));
}
__device__ __forceinline__ void mma16816(float* d, const uint32_t* a, const uint32_t* b) {
    asm volatile("mma.sync.aligned.m16n8k16.row.col.f32.bf16.bf16.f32 "
        "{%0,%1,%2,%3}, {%4,%5,%6,%7}, {%8,%9}, {%0,%1,%2,%3};"
        : "+f"(d[0]), "+f"(d[1]), "+f"(d[2]), "+f"(d[3])
        : "r"(a[0]), "r"(a[1]), "r"(a[2]), "r"(a[3]), "r"(b[0]), "r"(b[1]));
}
__device__ __forceinline__ void split2(float v, uint16_t& h, uint16_t& m) {
    __nv_bfloat16 bh = __float2bfloat16_rn(v);
    __nv_bfloat16 bm = __float2bfloat16_rn(v - __bfloat162float(bh));
    h = __bfloat16_as_ushort(bh); m = __bfloat16_as_ushort(bm);
}

__global__ void k_setup(const float* __restrict__ localP, const float* __restrict__ globalP,
                        const float* __restrict__ W, const float* __restrict__ bias) {
    int b = blockIdx.x, t = threadIdx.x;  // 384 thr
    if (b < KT) {
        const float* src = (b < MM) ? (localP + b * DD) : (globalP + (b - MM) * DD);
        float v = (t < DD) ? src[t] : 0.0f; float ss = v * v;
        #pragma unroll
        for (int o = 16; o; o >>= 1) ss += __shfl_xor_sync(0xffffffffu, ss, o);
        __shared__ float tot; if (t == 0) tot = 0.0f; __syncthreads();
        if ((t & 31) == 0) atomicAdd(&tot, ss); __syncthreads();
        float rinv = rsqrtf(fmaxf(tot, 1e-12f));
        if (t < DD) {
            uint16_t h, m; split2(v * rinv, h, m);
            int ch = t / KCH, kk = t % KCH;
            g_pB[ch][0][b * SK + kk] = __ushort_as_bfloat16(h);
            g_pB[ch][1][b * SK + kk] = __ushort_as_bfloat16(m);
        }
    } else if (b < KT + MM) {
        int m = b - KT; __shared__ float gp[DD]; __shared__ float lin[2 * DD];
        if (t < DD) gp[t] = globalP[m * DD + t]; __syncthreads();
        float acc = bias[t];
        for (int k = 0; k < DD; k++) acc += gp[k] * W[k * (2 * DD) + t];
        lin[t] = acc; __syncthreads();
        if (t < DD) { float z = lin[t + DD]; g_gated[m * DD + t] = lin[t] * (1.0f / (1.0f + __expf(-z))); }
    } else {
        if (t < KT) { g_cs1[t] = 0.0f; g_cs2[t] = 0.0f; g_cs3[t] = 0.0f; }
        if (t < MM) g_lastIdx[t] = -1;
    }
}

// ---- tensor GEMM: per CTA 128x256x192, 3-term split-bf16 (hh,hm,mh) -------
#define A_BY (BR * SK * 2)         // 18432
#define B_BY (KT * SK * 2)         // 36864
#define SM_A 0
#define SM_B (2 * A_BY)            // 36864
#define SM_RSS 110592              // float[128][2] row sumsq partials
#define STG_S 260
#define SM_RS 133120
#define SM_AS 133632
#define SM_CS 134144
#define SMEMTOT 135168

__global__ __launch_bounds__(256, 1) void k_tc(const float* __restrict__ x, int n) {
    extern __shared__ char smem[];
    uint32_t sb = (uint32_t)__cvta_generic_to_shared(smem);
    int tid = threadIdx.x, r0 = blockIdx.x * BR;
    int w = tid >> 5, lane = tid & 31;
    int wm = w >> 2, wn = w & 3;          // warp grid 2(M) x 4(N), warp tile 64x64
    int g = lane >> 2, q = lane & 3;

    float d[4][8][4];                      // 128 fp32 accumulators
    #pragma unroll
    for (int i = 0; i < 4; i++)
        #pragma unroll
        for (int j = 0; j < 8; j++)
            #pragma unroll
            for (int k = 0; k < 4; k++) d[i][j][k] = 0.0f;

    const int nb_for_a[2] = {2, 1};        // ah:{bh,bm}  am:{bh}
    float ssq = 0.0f;                      // fused row-norm partial (96 cols)

    for (int ch = 0; ch < NCH; ch++) {
        #pragma unroll
        for (int t2 = 0; t2 < 2; t2++) {   // B splits: contiguous cp.async
            const char* src = (const char*)&g_pB[ch][t2][0];
            #pragma unroll
            for (int i = 0; i < 9; i++) {
                int idx = tid + i * 256;   // 2304 chunks of 16B per image
                cpa16(sb + SM_B + t2 * B_BY + idx * 16, src + idx * 16);
            }
        }
        cpacm();
        {   // A splits: load x fp32, 2-way split, STS; accumulate sumsq
            int row = tid >> 1, kb = (tid & 1) * 32;
            const float4* xs = (const float4*)(x + (size_t)(r0 + row) * DD + ch * KCH + kb);
            #pragma unroll
            for (int p = 0; p < 8; p++) {
                float4 v = xs[p];
                ssq += v.x * v.x + v.y * v.y + v.z * v.z + v.w * v.w;
                uint16_t h0, m0, h1, m1;
                int o0 = (row * SK + kb + p * 4) * 2, o1 = o0 + 4;
                split2(v.x, h0, m0); split2(v.y, h1, m1);
                *(uint32_t*)(smem + SM_A + 0 * A_BY + o0) = ((uint32_t)h1 << 16) | h0;
                *(uint32_t*)(smem + SM_A + 1 * A_BY + o0) = ((uint32_t)m1 << 16) | m0;
                split2(v.z, h0, m0); split2(v.w, h1, m1);
                *(uint32_t*)(smem + SM_A + 0 * A_BY + o1) = ((uint32_t)h1 << 16) | h0;
                *(uint32_t*)(smem + SM_A + 1 * A_BY + o1) = ((uint32_t)m1 << 16) | m0;
            }
        }
        cpaw<0>();
        __syncthreads();

        #pragma unroll
        for (int ks = 0; ks < 4; ks++) {
            int kc = ks * 16 + q * 2;
            #pragma unroll
            for (int ta = 0; ta < 2; ta++) {
                uint32_t af[4][4];
                const char* Ab = smem + SM_A + ta * A_BY;
                #pragma unroll
                for (int mt = 0; mt < 4; mt++) {
                    int rr = wm * 64 + mt * 16 + g;
                    af[mt][0] = *(const uint32_t*)(Ab + (rr * SK + kc) * 2);
                    af[mt][1] = *(const uint32_t*)(Ab + ((rr + 8) * SK + kc) * 2);
                    af[mt][2] = *(const uint32_t*)(Ab + (rr * SK + kc + 8) * 2);
                    af[mt][3] = *(const uint32_t*)(Ab + ((rr + 8) * SK + kc + 8) * 2);
                }
                #pragma unroll
                for (int tb = 0; tb < 2; tb++) {
                    if (tb >= nb_for_a[ta]) break;
                    uint32_t bf[8][2];
                    const char* Bb = smem + SM_B + tb * B_BY;
                    #pragma unroll
                    for (int nt = 0; nt < 8; nt++) {
                        int nn = wn * 64 + nt * 8 + g;
                        bf[nt][0] = *(const uint32_t*)(Bb + (nn * SK + kc) * 2);
                        bf[nt][1] = *(const uint32_t*)(Bb + (nn * SK + kc + 8) * 2);
                    }
                    #pragma unroll
                    for (int mt = 0; mt < 4; mt++)
                        #pragma unroll
                        for (int nt = 0; nt < 8; nt++)
                            mma16816(d[mt][nt], af[mt], bf[nt]);
                }
            }
        }
        __syncthreads();                   // tiles reused next chunk
    }

    // ---- fused row norms: combine the two 96-col partials per row ---------
    float* RSS = (float*)(smem + SM_RSS);
    float* RS  = (float*)(smem + SM_RS);
    float* AS  = (float*)(smem + SM_AS);
    float* CS  = (float*)(smem + SM_CS);
    RSS[(tid >> 1) * 2 + (tid & 1)] = ssq;
    if (tid < 128) RS[tid] = 0.0f;
    if (tid < 256) CS[tid] = 0.0f;
    __syncthreads();
    float scv[4][2];
    #pragma unroll
    for (int mt = 0; mt < 4; mt++) {
        int rlo = wm * 64 + mt * 16 + g, rhi = rlo + 8;
        scv[mt][0] = rsqrtf(fmaxf(RSS[rlo * 2] + RSS[rlo * 2 + 1], 1e-12f)) * TINV;
        scv[mt][1] = rsqrtf(fmaxf(RSS[rhi * 2] + RSS[rhi * 2 + 1], 1e-12f)) * TINV;
    }
    __syncthreads();   // RSS dead; stg region may now overwrite it

    // ---- epilogue: exp + rowsum + stage; then coalesced E store + colsum --
    float* stg = (float*)smem;             // [128][260]
    #pragma unroll
    for (int mt = 0; mt < 4; mt++) {
        int rlo = wm * 64 + mt * 16 + g, rhi = rlo + 8;
        float slo = scv[mt][0], shi = scv[mt][1];
        float rs0 = 0.0f, rs1 = 0.0f;
        #pragma unroll
        for (int nt = 0; nt < 8; nt++) {
            int nn = wn * 64 + nt * 8 + q * 2;
            float e0 = __expf(d[mt][nt][0] * slo);
            float e1 = __expf(d[mt][nt][1] * slo);
            float e2 = __expf(d[mt][nt][2] * shi);
            float e3 = __expf(d[mt][nt][3] * shi);
            rs0 += e0 + e1; rs1 += e2 + e3;
            *(float2*)(stg + rlo * STG_S + nn) = make_float2(e0, e1);
            *(float2*)(stg + rhi * STG_S + nn) = make_float2(e2, e3);
        }
        atomicAdd(&RS[rlo], rs0); atomicAdd(&RS[rhi], rs1);
    }
    __syncthreads();
    if (tid < 128) AS[tid] = 1.0f / ((float)n * RS[tid]);
    __syncthreads();
    {
        int rr = tid >> 6, cc = (tid & 63) * 4;
        float c0 = 0, c1 = 0, c2 = 0, c3 = 0;
        #pragma unroll 4
        for (int rb = 0; rb < 32; rb++) {
            int r = rb * 4 + rr;
            float4 v = *(const float4*)(stg + r * STG_S + cc);
            *(float4*)(g_E + (size_t)(r0 + r) * KT + cc) = v;
            float a = AS[r];
            c0 += a * v.x; c1 += a * v.y; c2 += a * v.z; c3 += a * v.w;
        }
        atomicAdd(&CS[cc + 0], c0); atomicAdd(&CS[cc + 1], c1);
        atomicAdd(&CS[cc + 2], c2); atomicAdd(&CS[cc + 3], c3);
        __syncthreads();
        if (tid < KT) atomicAdd(&g_cs1[tid], CS[tid]);
    }
}

template<int P>
__global__ void k_pass(int n) {
    const float* ci = (P == 1) ? g_cs1 : g_cs2; float* co = (P == 1) ? g_cs2 : g_cs3;
    int lane = threadIdx.x & 31, warp = (blockIdx.x * blockDim.x + threadIdx.x) >> 5, nw = (gridDim.x * blockDim.x) >> 5;
    float bb[8];
    #pragma unroll
    for (int j = 0; j < 8; j++) bb[j] = 1.0f / ((float)KT * ci[lane * 8 + j]);
    float ca[8] = {0, 0, 0, 0, 0, 0, 0, 0};
    float ninv = 1.0f / (float)n;
    for (int rg = warp * 4; rg < n; rg += nw * 4) {
        float4 e[4][2];
        #pragma unroll
        for (int r = 0; r < 4; r++) {
            const float4* er = (const float4*)(g_E + (size_t)(rg + r) * KT) + lane * 2;
            e[r][0] = er[0]; e[r][1] = er[1];
        }
        #pragma unroll
        for (int r = 0; r < 4; r++) {
            float s = e[r][0].x * bb[0] + e[r][0].y * bb[1] + e[r][0].z * bb[2] + e[r][0].w * bb[3]
                    + e[r][1].x * bb[4] + e[r][1].y * bb[5] + e[r][1].z * bb[6] + e[r][1].w * bb[7];
            #pragma unroll
            for (int o = 16; o; o >>= 1) s += __shfl_xor_sync(0xffffffffu, s, o);
            float a = ninv / s;
            ca[0] += a * e[r][0].x; ca[1] += a * e[r][0].y; ca[2] += a * e[r][0].z; ca[3] += a * e[r][0].w;
            ca[4] += a * e[r][1].x; ca[5] += a * e[r][1].y; ca[6] += a * e[r][1].z; ca[7] += a * e[r][1].w;
        }
    }
    __shared__ float sa[KT];
    if (threadIdx.x < KT) sa[threadIdx.x] = 0.0f;
    __syncthreads();
    #pragma unroll
    for (int j = 0; j < 8; j++) atomicAdd(&sa[lane * 8 + j], ca[j]);
    __syncthreads();
    if (threadIdx.x < KT) atomicAdd(&co[threadIdx.x], sa[threadIdx.x]);
}

__global__ void k_final(const float* __restrict__ x, float* __restrict__ out, int n) {
    int lane = threadIdx.x & 31, warp = (blockIdx.x * blockDim.x + threadIdx.x) >> 5, nw = (gridDim.x * blockDim.x) >> 5;
    float bb[8];
    #pragma unroll
    for (int j = 0; j < 8; j++) bb[j] = 1.0f / ((float)KT * g_cs3[lane * 8 + j]);
    for (int rg = warp * 2; rg < n; rg += nw * 2) {
        float4 e[2][2];
        #pragma unroll
        for (int r = 0; r < 2; r++) {
            const float4* er = (const float4*)(g_E + (size_t)(rg + r) * KT) + lane * 2;
            e[r][0] = er[0]; e[r][1] = er[1];
        }
        #pragma unroll
        for (int r = 0; r < 2; r++) {
            int row = rg + r;
            float v[8] = { e[r][0].x * bb[0], e[r][0].y * bb[1], e[r][0].z * bb[2], e[r][0].w * bb[3],
                           e[r][1].x * bb[4], e[r][1].y * bb[5], e[r][1].z * bb[6], e[r][1].w * bb[7] };
            float best = v[0]; int bi = lane * 8;
            #pragma unroll
            for (int j = 1; j < 8; j++) if (v[j] > best) { best = v[j]; bi = lane * 8 + j; }
            #pragma unroll
            for (int o = 1; o < 16; o <<= 1) {
                float ob = __shfl_xor_sync(0xffffffffu, best, o);
                int  obi = __shfl_xor_sync(0xffffffffu, bi, o);
                if (ob > best || (ob == best && obi < bi)) { best = ob; bi = obi; }
            }
            int lidx = __shfl_sync(0xffffffffu, bi, 0);
            int gidx = __shfl_sync(0xffffffffu, bi, 16) - MM;
            if (lane == 0) atomicMax(&g_lastIdx[lidx], row);
            const float* xr = x + (size_t)row * DD;
            const float* gt = g_gated + (size_t)gidx * DD;
            float o6[6]; float ss = 0.0f;
            #pragma unroll
            for (int k = 0; k < 6; k++) { float ov = 0.5f * (gt[lane + 32 * k] + xr[lane + 32 * k]); o6[k] = ov; ss += ov * ov; }
            #pragma unroll
            for (int o = 16; o; o >>= 1) ss += __shfl_xor_sync(0xffffffffu, ss, o);
            float rinv = rsqrtf(fmaxf(ss, 1e-12f));
            float* orow = out + (size_t)row * DD;
            #pragma unroll
            for (int k = 0; k < 6; k++) orow[lane + 32 * k] = o6[k] * rinv;
        }
    }
}

__global__ void k_ema(const float* __restrict__ x, const float* __restrict__ localP,
                      float* __restrict__ outLocal) {
    int m = blockIdx.x, t = threadIdx.x;
    int i = g_lastIdx[m];
    float lv = localP[m * DD + t];
    outLocal[m * DD + t] = (i >= 0) ? (0.96f * lv + 0.04f * x[(size_t)i * DD + t]) : lv;
}

extern "C" void kernel_launch(void* const* d_in, const int* in_sizes, int n_in,
                              void* d_out, int out_size) {
    const float* proj = (const float*)d_in[0];
    const float* localP = (const float*)d_in[1];
    const float* globalP = (const float*)d_in[2];
    const float* W = (const float*)d_in[3];
    const float* bias = (const float*)d_in[4];
    float* out = (float*)d_out;
    int n = in_sizes[0] / DD;
    float* outLocal = out + (size_t)in_sizes[0];

    cudaFuncSetAttribute(k_tc, cudaFuncAttributeMaxDynamicSharedMemorySize, SMEMTOT);

    k_setup<<<KT + MM + 1, 2 * DD>>>(localP, globalP, W, bias);
    k_tc<<<n / BR, 256, SMEMTOT>>>(proj, n);
    k_pass<1><<<1024, 256>>>(n);
    k_pass<2><<<1024, 256>>>(n);
    k_final<<<1024, 256>>>(proj, out, n);
    k_ema<<<MM, DD>>>(proj, localP, outLocal);
}

// round 16
// speedup vs baseline: 1.9550x; 1.0330x over previous
#include <cuda_runtime.h>
#include <cuda_bf16.h>
#include <cstdint>

#define DD 192
#define MM 128
#define KT 256
#define TINV 20.0f
#define BR 128
#define KCH 64
#define NCH 3
#define SK 72

__device__ float g_E[(size_t)131072 * KT];
__device__ __align__(16) __nv_bfloat16 g_pB[NCH][2][KT * SK];
__device__ float g_gated[MM * DD];
__device__ float g_cs1[KT], g_cs2[KT], g_cs3[KT];
__device__ int g_lastIdx[MM];

__device__ __forceinline__ void cpa16(uint32_t s, const void* g) {
    asm volatile("cp.async.cg.shared.global [%0], [%1], 16;" :: "r"(s), "l"(g));
}
__device__ __forceinline__ void cpacm() { asm volatile("cp.async.commit_group;"); }
template<int N> __device__ __forceinline__ void cpaw() {
    asm volatile("cp.async.wait_group %0;" :: "n"(N));
}
__device__ __forceinline__ void mma16816(float* d, const uint32_t* a, const uint32_t* b) {
    asm volatile("mma.sync.aligned.m16n8k16.row.col.f32.bf16.bf16.f32 "
        "{%0,%1,%2,%3}, {%4,%5,%6,%7}, {%8,%9}, {%0,%1,%2,%3};"
        : "+f"(d[0]), "+f"(d[1]), "+f"(d[2]), "+f"(d[3])
        : "r"(a[0]), "r"(a[1]), "r"(a[2]), "r"(a[3]), "r"(b[0]), "r"(b[1]));
}
__device__ __forceinline__ void split2(float v, uint16_t& h, uint16_t& m) {
    __nv_bfloat16 bh = __float2bfloat16_rn(v);
    __nv_bfloat16 bm = __float2bfloat16_rn(v - __bfloat162float(bh));
    h = __bfloat16_as_ushort(bh); m = __bfloat16_as_ushort(bm);
}

__global__ void k_setup(const float* __restrict__ localP, const float* __restrict__ globalP,
                        const float* __restrict__ W, const float* __restrict__ bias) {
    int b = blockIdx.x, t = threadIdx.x;
    if (b < KT) {
        const float* src = (b < MM) ? (localP + b * DD) : (globalP + (b - MM) * DD);
        float v = (t < DD) ? src[t] : 0.0f; float ss = v * v;
        #pragma unroll
        for (int o = 16; o; o >>= 1) ss += __shfl_xor_sync(0xffffffffu, ss, o);
        __shared__ float tot; if (t == 0) tot = 0.0f; __syncthreads();
        if ((t & 31) == 0) atomicAdd(&tot, ss); __syncthreads();
        float rinv = rsqrtf(fmaxf(tot, 1e-12f));
        if (t < DD) {
            uint16_t h, m; split2(v * rinv, h, m);
            int ch = t / KCH, kk = t % KCH;
            g_pB[ch][0][b * SK + kk] = __ushort_as_bfloat16(h);
            g_pB[ch][1][b * SK + kk] = __ushort_as_bfloat16(m);
        }
    } else if (b < KT + MM) {
        int m = b - KT; __shared__ float gp[DD]; __shared__ float lin[2 * DD];
        if (t < DD) gp[t] = globalP[m * DD + t]; __syncthreads();
        float acc = bias[t];
        for (int k = 0; k < DD; k++) acc += gp[k] * W[k * (2 * DD) + t];
        lin[t] = acc; __syncthreads();
        if (t < DD) { float z = lin[t + DD]; g_gated[m * DD + t] = lin[t] * (1.0f / (1.0f + __expf(-z))); }
    } else {
        if (t < KT) { g_cs1[t] = 0.0f; g_cs2[t] = 0.0f; g_cs3[t] = 0.0f; }
        if (t < MM) g_lastIdx[t] = -1;
    }
}

// ---- tensor GEMM: 128x256x192/CTA, 3-term split-bf16, chunk-pipelined -----
#define A_BY (BR * SK * 2)          // 18432
#define B_BY (KT * SK * 2)          // 36864
#define ST_BY 110592                // one stage: 2*A_BY + 2*B_BY
#define STG_S 260
#define SM_RSS 133120
#define SM_RS 134144
#define SM_AS 134656
#define SM_CS 135168
#define SMEMTOT 221184

__global__ __launch_bounds__(256, 1) void k_tc(const float* __restrict__ x, int n) {
    extern __shared__ char smem[];
    uint32_t sb = (uint32_t)__cvta_generic_to_shared(smem);
    int tid = threadIdx.x, r0 = blockIdx.x * BR;
    int w = tid >> 5, lane = tid & 31;
    int wm = w >> 2, wn = w & 3;
    int g = lane >> 2, q = lane & 3;
    int arow = tid >> 1, akb = (tid & 1) * 32;

    float d[4][8][4];
    #pragma unroll
    for (int i = 0; i < 4; i++)
        #pragma unroll
        for (int j = 0; j < 8; j++)
            #pragma unroll
            for (int k = 0; k < 4; k++) d[i][j][k] = 0.0f;

    float4 xr[8];
    float ssq = 0.0f;
    const int nb_for_a[2] = {2, 1};

    // prologue: chunk 0 into stage 0
    {
        const float4* xs = (const float4*)(x + (size_t)(r0 + arow) * DD + akb);
        #pragma unroll
        for (int p = 0; p < 8; p++) xr[p] = xs[p];
        #pragma unroll
        for (int t2 = 0; t2 < 2; t2++) {
            const char* src = (const char*)&g_pB[0][t2][0];
            #pragma unroll
            for (int i = 0; i < 9; i++) {
                int idx = tid + i * 256;
                cpa16(sb + 36864 + t2 * B_BY + idx * 16, src + idx * 16);
            }
        }
        cpacm();
        char* Ab = smem;
        #pragma unroll
        for (int p = 0; p < 8; p++) {
            float4 v = xr[p];
            ssq += v.x * v.x + v.y * v.y + v.z * v.z + v.w * v.w;
            uint16_t h0, m0, h1, m1;
            int o0 = (arow * SK + akb + p * 4) * 2, o1 = o0 + 4;
            split2(v.x, h0, m0); split2(v.y, h1, m1);
            *(uint32_t*)(Ab + o0) = ((uint32_t)h1 << 16) | h0;
            *(uint32_t*)(Ab + A_BY + o0) = ((uint32_t)m1 << 16) | m0;
            split2(v.z, h0, m0); split2(v.w, h1, m1);
            *(uint32_t*)(Ab + o1) = ((uint32_t)h1 << 16) | h0;
            *(uint32_t*)(Ab + A_BY + o1) = ((uint32_t)m1 << 16) | m0;
        }
        cpaw<0>();
        __syncthreads();
    }

    for (int ch = 0; ch < NCH; ch++) {
        int st = ch & 1;
        if (ch < NCH - 1) {   // prefetch next chunk: x->regs, B->cp.async (other stage)
            const float4* xs = (const float4*)(x + (size_t)(r0 + arow) * DD + (ch + 1) * KCH + akb);
            #pragma unroll
            for (int p = 0; p < 8; p++) xr[p] = xs[p];
            #pragma unroll
            for (int t2 = 0; t2 < 2; t2++) {
                const char* src = (const char*)&g_pB[ch + 1][t2][0];
                #pragma unroll
                for (int i = 0; i < 9; i++) {
                    int idx = tid + i * 256;
                    cpa16(sb + (st ^ 1) * ST_BY + 36864 + t2 * B_BY + idx * 16, src + idx * 16);
                }
            }
            cpacm();
        }
        const char* SA = smem + st * ST_BY;
        const char* SB = SA + 36864;
        #pragma unroll
        for (int ks = 0; ks < 4; ks++) {
            int kc = ks * 16 + q * 2;
            #pragma unroll
            for (int ta = 0; ta < 2; ta++) {
                uint32_t af[4][4];
                const char* Ab = SA + ta * A_BY;
                #pragma unroll
                for (int mt = 0; mt < 4; mt++) {
                    int rr = wm * 64 + mt * 16 + g;
                    af[mt][0] = *(const uint32_t*)(Ab + (rr * SK + kc) * 2);
                    af[mt][1] = *(const uint32_t*)(Ab + ((rr + 8) * SK + kc) * 2);
                    af[mt][2] = *(const uint32_t*)(Ab + (rr * SK + kc + 8) * 2);
                    af[mt][3] = *(const uint32_t*)(Ab + ((rr + 8) * SK + kc + 8) * 2);
                }
                #pragma unroll
                for (int tb = 0; tb < 2; tb++) {
                    if (tb >= nb_for_a[ta]) break;
                    uint32_t bf[8][2];
                    const char* Bb = SB + tb * B_BY;
                    #pragma unroll
                    for (int nt = 0; nt < 8; nt++) {
                        int nn = wn * 64 + nt * 8 + g;
                        bf[nt][0] = *(const uint32_t*)(Bb + (nn * SK + kc) * 2);
                        bf[nt][1] = *(const uint32_t*)(Bb + (nn * SK + kc + 8) * 2);
                    }
                    #pragma unroll
                    for (int mt = 0; mt < 4; mt++)
                        #pragma unroll
                        for (int nt = 0; nt < 8; nt++)
                            mma16816(d[mt][nt], af[mt], bf[nt]);
                }
            }
        }
        if (ch < NCH - 1) {   // split prefetched x into the other stage
            char* Ab = smem + (st ^ 1) * ST_BY;
            #pragma unroll
            for (int p = 0; p < 8; p++) {
                float4 v = xr[p];
                ssq += v.x * v.x + v.y * v.y + v.z * v.z + v.w * v.w;
                uint16_t h0, m0, h1, m1;
                int o0 = (arow * SK + akb + p * 4) * 2, o1 = o0 + 4;
                split2(v.x, h0, m0); split2(v.y, h1, m1);
                *(uint32_t*)(Ab + o0) = ((uint32_t)h1 << 16) | h0;
                *(uint32_t*)(Ab + A_BY + o0) = ((uint32_t)m1 << 16) | m0;
                split2(v.z, h0, m0); split2(v.w, h1, m1);
                *(uint32_t*)(Ab + o1) = ((uint32_t)h1 << 16) | h0;
                *(uint32_t*)(Ab + A_BY + o1) = ((uint32_t)m1 << 16) | m0;
            }
        }
        cpaw<0>();
        __syncthreads();
    }

    // ---- fused row norms ----
    float* RSS = (float*)(smem + SM_RSS);
    float* RS  = (float*)(smem + SM_RS);
    float* AS  = (float*)(smem + SM_AS);
    float* CS  = (float*)(smem + SM_CS);
    RSS[arow * 2 + (tid & 1)] = ssq;
    if (tid < 128) RS[tid] = 0.0f;
    if (tid < 256) CS[tid] = 0.0f;
    __syncthreads();
    float scv[4][2];
    #pragma unroll
    for (int mt = 0; mt < 4; mt++) {
        int rlo = wm * 64 + mt * 16 + g, rhi = rlo + 8;
        scv[mt][0] = rsqrtf(fmaxf(RSS[rlo * 2] + RSS[rlo * 2 + 1], 1e-12f)) * TINV;
        scv[mt][1] = rsqrtf(fmaxf(RSS[rhi * 2] + RSS[rhi * 2 + 1], 1e-12f)) * TINV;
    }
    __syncthreads();

    // ---- epilogue: exp + rowsum + stage; coalesced E store + colsum ----
    float* stg = (float*)smem;
    #pragma unroll
    for (int mt = 0; mt < 4; mt++) {
        int rlo = wm * 64 + mt * 16 + g, rhi = rlo + 8;
        float slo = scv[mt][0], shi = scv[mt][1];
        float rs0 = 0.0f, rs1 = 0.0f;
        #pragma unroll
        for (int nt = 0; nt < 8; nt++) {
            int nn = wn * 64 + nt * 8 + q * 2;
            float e0 = __expf(d[mt][nt][0] * slo);
            float e1 = __expf(d[mt][nt][1] * slo);
            float e2 = __expf(d[mt][nt][2] * shi);
            float e3 = __expf(d[mt][nt][3] * shi);
            rs0 += e0 + e1; rs1 += e2 + e3;
            *(float2*)(stg + rlo * STG_S + nn) = make_float2(e0, e1);
            *(float2*)(stg + rhi * STG_S + nn) = make_float2(e2, e3);
        }
        atomicAdd(&RS[rlo], rs0); atomicAdd(&RS[rhi], rs1);
    }
    __syncthreads();
    if (tid < 128) AS[tid] = 1.0f / ((float)n * RS[tid]);
    __syncthreads();
    {
        int rr = tid >> 6, cc = (tid & 63) * 4;
        float c0 = 0, c1 = 0, c2 = 0, c3 = 0;
        #pragma unroll 4
        for (int rb = 0; rb < 32; rb++) {
            int r = rb * 4 + rr;
            float4 v = *(const float4*)(stg + r * STG_S + cc);
            *(float4*)(g_E + (size_t)(r0 + r) * KT + cc) = v;
            float a = AS[r];
            c0 += a * v.x; c1 += a * v.y; c2 += a * v.z; c3 += a * v.w;
        }
        atomicAdd(&CS[cc + 0], c0); atomicAdd(&CS[cc + 1], c1);
        atomicAdd(&CS[cc + 2], c2); atomicAdd(&CS[cc + 3], c3);
        __syncthreads();
        if (tid < KT) atomicAdd(&g_cs1[tid], CS[tid]);
    }
}

// ---- sinkhorn pass: cp.async double-buffered 32-row tiles ----------------
#define PTILE 32
#define PASS_SMEM ((2 * PTILE * KT + KT) * 4)   // 66560 B

template<int P>
__global__ __launch_bounds__(256, 3) void k_pass(int n) {
    const float* ci = (P == 1) ? g_cs1 : g_cs2; float* co = (P == 1) ? g_cs2 : g_cs3;
    extern __shared__ float pbuf[];
    float* sa = pbuf + 2 * PTILE * KT;
    int tid = threadIdx.x, lane = tid & 31, w = tid >> 5;
    uint32_t sbb[2];
    sbb[0] = (uint32_t)__cvta_generic_to_shared(pbuf);
    sbb[1] = (uint32_t)__cvta_generic_to_shared(pbuf + PTILE * KT);

    float bb[8];
    #pragma unroll
    for (int j = 0; j < 8; j++) bb[j] = 1.0f / ((float)KT * ci[lane + 32 * j]);
    float ca[8] = {0, 0, 0, 0, 0, 0, 0, 0};
    float ninv = 1.0f / (float)n;
    int ntiles = n >> 5;

    // prologue: tile blockIdx.x -> stage 0
    {
        const float* src = g_E + (size_t)blockIdx.x * PTILE * KT;
        #pragma unroll
        for (int i = 0; i < 8; i++) cpa16(sbb[0] + (tid + i * 256) * 16, src + (tid + i * 256) * 4);
        cpacm();
    }
    int it = 0;
    for (int t = blockIdx.x; t < ntiles; t += gridDim.x, it++) {
        int st = it & 1;
        int nt = t + gridDim.x;
        if (nt < ntiles) {
            const float* src = g_E + (size_t)nt * PTILE * KT;
            #pragma unroll
            for (int i = 0; i < 8; i++) cpa16(sbb[st ^ 1] + (tid + i * 256) * 16, src + (tid + i * 256) * 4);
        }
        cpacm();
        cpaw<1>();
        __syncthreads();
        const float* B = pbuf + st * PTILE * KT;
        #pragma unroll
        for (int r = 0; r < 4; r++) {
            int row = w * 4 + r;
            float v[8];
            #pragma unroll
            for (int j = 0; j < 8; j++) v[j] = B[row * KT + lane + 32 * j];   // LDS.32, bank=lane
            float s = v[0] * bb[0] + v[1] * bb[1] + v[2] * bb[2] + v[3] * bb[3]
                    + v[4] * bb[4] + v[5] * bb[5] + v[6] * bb[6] + v[7] * bb[7];
            #pragma unroll
            for (int o = 16; o; o >>= 1) s += __shfl_xor_sync(0xffffffffu, s, o);
            float a = ninv / s;
            #pragma unroll
            for (int j = 0; j < 8; j++) ca[j] += a * v[j];
        }
        __syncthreads();
    }
    if (tid < KT) sa[tid] = 0.0f;
    __syncthreads();
    #pragma unroll
    for (int j = 0; j < 8; j++) atomicAdd(&sa[lane + 32 * j], ca[j]);
    __syncthreads();
    if (tid < KT) atomicAdd(&co[tid], sa[tid]);
}

__global__ void k_final(const float* __restrict__ x, float* __restrict__ out, int n) {
    int lane = threadIdx.x & 31, warp = (blockIdx.x * blockDim.x + threadIdx.x) >> 5, nw = (gridDim.x * blockDim.x) >> 5;
    float bb[8];
    #pragma unroll
    for (int j = 0; j < 8; j++) bb[j] = 1.0f / ((float)KT * g_cs3[lane * 8 + j]);
    for (int rg = warp * 2; rg < n; rg += nw * 2) {
        float4 e[2][2];
        #pragma unroll
        for (int r = 0; r < 2; r++) {
            const float4* er = (const float4*)(g_E + (size_t)(rg + r) * KT) + lane * 2;
            e[r][0] = er[0]; e[r][1] = er[1];
        }
        #pragma unroll
        for (int r = 0; r < 2; r++) {
            int row = rg + r;
            float v[8] = { e[r][0].x * bb[0], e[r][0].y * bb[1], e[r][0].z * bb[2], e[r][0].w * bb[3],
                           e[r][1].x * bb[4], e[r][1].y * bb[5], e[r][1].z * bb[6], e[r][1].w * bb[7] };
            float best = v[0]; int bi = lane * 8;
            #pragma unroll
            for (int j = 1; j < 8; j++) if (v[j] > best) { best = v[j]; bi = lane * 8 + j; }
            #pragma unroll
            for (int o = 1; o < 16; o <<= 1) {
                float ob = __shfl_xor_sync(0xffffffffu, best, o);
                int  obi = __shfl_xor_sync(0xffffffffu, bi, o);
                if (ob > best || (ob == best && obi < bi)) { best = ob; bi = obi; }
            }
            int lidx = __shfl_sync(0xffffffffu, bi, 0);
            int gidx = __shfl_sync(0xffffffffu, bi, 16) - MM;
            if (lane == 0) atomicMax(&g_lastIdx[lidx], row);
            const float* xr = x + (size_t)row * DD;
            const float* gt = g_gated + (size_t)gidx * DD;
            float o6[6]; float ss = 0.0f;
            #pragma unroll
            for (int k = 0; k < 6; k++) { float ov = 0.5f * (gt[lane + 32 * k] + xr[lane + 32 * k]); o6[k] = ov; ss += ov * ov; }
            #pragma unroll
            for (int o = 16; o; o >>= 1) ss += __shfl_xor_sync(0xffffffffu, ss, o);
            float rinv = rsqrtf(fmaxf(ss, 1e-12f));
            float* orow = out + (size_t)row * DD;
            #pragma unroll
            for (int k = 0; k < 6; k++) orow[lane + 32 * k] = o6[k] * rinv;
        }
    }
}

__global__ void k_ema(const float* __restrict__ x, const float* __restrict__ localP,
                      float* __restrict__ outLocal) {
    int m = blockIdx.x, t = threadIdx.x;
    int i = g_lastIdx[m];
    float lv = localP[m * DD + t];
    outLocal[m * DD + t] = (i >= 0) ? (0.96f * lv + 0.04f * x[(size_t)i * DD + t]) : lv;
}

extern "C" void kernel_launch(void* const* d_in, const int* in_sizes, int n_in,
                              void* d_out, int out_size) {
    const float* proj = (const float*)d_in[0];
    const float* localP = (const float*)d_in[1];
    const float* globalP = (const float*)d_in[2];
    const float* W = (const float*)d_in[3];
    const float* bias = (const float*)d_in[4];
    float* out = (float*)d_out;
    int n = in_sizes[0] / DD;
    float* outLocal = out + (size_t)in_sizes[0];

    cudaFuncSetAttribute(k_tc, cudaFuncAttributeMaxDynamicSharedMemorySize, SMEMTOT);
    cudaFuncSetAttribute(k_pass<1>, cudaFuncAttributeMaxDynamicSharedMemorySize, PASS_SMEM);
    cudaFuncSetAttribute(k_pass<2>, cudaFuncAttributeMaxDynamicSharedMemorySize, PASS_SMEM);

    k_setup<<<KT + MM + 1, 2 * DD>>>(localP, globalP, W, bias);
    k_tc<<<n / BR, 256, SMEMTOT>>>(proj, n);
    k_pass<1><<<444, 256, PASS_SMEM>>>(n);
    k_pass<2><<<444, 256, PASS_SMEM>>>(n);
    k_final<<<1024, 256>>>(proj, out, n);
    k_ema<<<MM, DD>>>(proj, localP, outLocal);
}

// round 17
// speedup vs baseline: 2.1496x; 1.0995x over previous
#include <cuda_runtime.h>
#include <cuda_bf16.h>
#include <cstdint>

#define DD 192
#define MM 128
#define KT 256
#define TINV 20.0f
#define BR 64
#define KCH 64
#define NCH 3
#define SK 72

__device__ float g_E[(size_t)131072 * KT];
__device__ __align__(16) __nv_bfloat16 g_pB[NCH][2][KT * SK];
__device__ float g_gated[MM * DD];
__device__ float g_cs1[KT], g_cs2[KT], g_cs3[KT];
__device__ int g_lastIdx[MM];

__device__ __forceinline__ void cpa16(uint32_t s, const void* g) {
    asm volatile("cp.async.cg.shared.global [%0], [%1], 16;" :: "r"(s), "l"(g));
}
__device__ __forceinline__ void cpacm() { asm volatile("cp.async.commit_group;"); }
template<int N> __device__ __forceinline__ void cpaw() {
    asm volatile("cp.async.wait_group %0;" :: "n"(N));
}
__device__ __forceinline__ void mma16816(float* d, const uint32_t* a, const uint32_t* b) {
    asm volatile("mma.sync.aligned.m16n8k16.row.col.f32.bf16.bf16.f32 "
        "{%0,%1,%2,%3}, {%4,%5,%6,%7}, {%8,%9}, {%0,%1,%2,%3};"
        : "+f"(d[0]), "+f"(d[1]), "+f"(d[2]), "+f"(d[3])
        : "r"(a[0]), "r"(a[1]), "r"(a[2]), "r"(a[3]), "r"(b[0]), "r"(b[1]));
}
__device__ __forceinline__ void split2(float v, uint16_t& h, uint16_t& m) {
    __nv_bfloat16 bh = __float2bfloat16_rn(v);
    __nv_bfloat16 bm = __float2bfloat16_rn(v - __bfloat162float(bh));
    h = __bfloat16_as_ushort(bh); m = __bfloat16_as_ushort(bm);
}

__global__ void k_setup(const float* __restrict__ localP, const float* __restrict__ globalP,
                        const float* __restrict__ W, const float* __restrict__ bias) {
    int b = blockIdx.x, t = threadIdx.x;
    if (b < KT) {
        const float* src = (b < MM) ? (localP + b * DD) : (globalP + (b - MM) * DD);
        float v = (t < DD) ? src[t] : 0.0f; float ss = v * v;
        #pragma unroll
        for (int o = 16; o; o >>= 1) ss += __shfl_xor_sync(0xffffffffu, ss, o);
        __shared__ float tot; if (t == 0) tot = 0.0f; __syncthreads();
        if ((t & 31) == 0) atomicAdd(&tot, ss); __syncthreads();
        float rinv = rsqrtf(fmaxf(tot, 1e-12f));
        if (t < DD) {
            uint16_t h, m; split2(v * rinv, h, m);
            int ch = t / KCH, kk = t % KCH;
            g_pB[ch][0][b * SK + kk] = __ushort_as_bfloat16(h);
            g_pB[ch][1][b * SK + kk] = __ushort_as_bfloat16(m);
        }
    } else if (b < KT + MM) {
        int m = b - KT; __shared__ float gp[DD]; __shared__ float lin[2 * DD];
        if (t < DD) gp[t] = globalP[m * DD + t]; __syncthreads();
        float acc = bias[t];
        for (int k = 0; k < DD; k++) acc += gp[k] * W[k * (2 * DD) + t];
        lin[t] = acc; __syncthreads();
        if (t < DD) { float z = lin[t + DD]; g_gated[m * DD + t] = lin[t] * (1.0f / (1.0f + __expf(-z))); }
    } else {
        if (t < KT) { g_cs1[t] = 0.0f; g_cs2[t] = 0.0f; g_cs3[t] = 0.0f; }
        if (t < MM) g_lastIdx[t] = -1;
    }
}

// ---- tensor GEMM: 64x256x192/CTA, 3-term split-bf16, 2 CTAs/SM ------------
#define A_BY (BR * SK * 2)          // 9216
#define B_BY (KT * SK * 2)          // 36864
#define SM_B (2 * A_BY)             // 18432 (A images at 0)
#define STG_S 260
#define SM_RSS 92160
#define SM_RS  93184
#define SM_AS  93440
#define SM_CS  93696
#define SMEMTOT 94720

__global__ __launch_bounds__(256, 2) void k_tc(const float* __restrict__ x, int n) {
    extern __shared__ char smem[];
    uint32_t sb = (uint32_t)__cvta_generic_to_shared(smem);
    int tid = threadIdx.x, r0 = blockIdx.x * BR;
    int w = tid >> 5, lane = tid & 31;
    int g = lane >> 2, q = lane & 3;
    int arow = tid >> 2, akp = (tid & 3) * 16;   // A-split: row 0..63, 16-col part

    float d[4][4][4];                            // warp tile 64(M) x 32(N)
    #pragma unroll
    for (int i = 0; i < 4; i++)
        #pragma unroll
        for (int j = 0; j < 4; j++)
            #pragma unroll
            for (int k = 0; k < 4; k++) d[i][j][k] = 0.0f;

    const int nb_for_a[2] = {2, 1};              // ah:{bh,bm}  am:{bh}
    float ssq = 0.0f;

    for (int ch = 0; ch < NCH; ch++) {
        // B: one contiguous 73728-B copy (both split images adjacent)
        const char* bsrc = (const char*)&g_pB[ch][0][0];
        #pragma unroll
        for (int i = 0; i < 18; i++) {
            int idx = tid + i * 256;             // 4608 chunks of 16B
            cpa16(sb + SM_B + idx * 16, bsrc + idx * 16);
        }
        cpacm();
        // A: load x fp32, 2-way split, STS; fused sumsq
        {
            const float4* xs = (const float4*)(x + (size_t)(r0 + arow) * DD + ch * KCH + akp);
            #pragma unroll
            for (int p = 0; p < 4; p++) {
                float4 v = xs[p];
                ssq += v.x * v.x + v.y * v.y + v.z * v.z + v.w * v.w;
                uint16_t h0, m0, h1, m1;
                int o0 = (arow * SK + akp + p * 4) * 2, o1 = o0 + 4;
                split2(v.x, h0, m0); split2(v.y, h1, m1);
                *(uint32_t*)(smem + o0) = ((uint32_t)h1 << 16) | h0;
                *(uint32_t*)(smem + A_BY + o0) = ((uint32_t)m1 << 16) | m0;
                split2(v.z, h0, m0); split2(v.w, h1, m1);
                *(uint32_t*)(smem + o1) = ((uint32_t)h1 << 16) | h0;
                *(uint32_t*)(smem + A_BY + o1) = ((uint32_t)m1 << 16) | m0;
            }
        }
        cpaw<0>();
        __syncthreads();

        #pragma unroll
        for (int ks = 0; ks < 4; ks++) {
            int kc = ks * 16 + q * 2;
            #pragma unroll
            for (int ta = 0; ta < 2; ta++) {
                uint32_t af[4][4];
                const char* Ab = smem + ta * A_BY;
                #pragma unroll
                for (int mt = 0; mt < 4; mt++) {
                    int rr = mt * 16 + g;
                    af[mt][0] = *(const uint32_t*)(Ab + (rr * SK + kc) * 2);
                    af[mt][1] = *(const uint32_t*)(Ab + ((rr + 8) * SK + kc) * 2);
                    af[mt][2] = *(const uint32_t*)(Ab + (rr * SK + kc + 8) * 2);
                    af[mt][3] = *(const uint32_t*)(Ab + ((rr + 8) * SK + kc + 8) * 2);
                }
                #pragma unroll
                for (int tb = 0; tb < 2; tb++) {
                    if (tb >= nb_for_a[ta]) break;
                    uint32_t bf[4][2];
                    const char* Bb = smem + SM_B + tb * B_BY;
                    #pragma unroll
                    for (int nt = 0; nt < 4; nt++) {
                        int nn = w * 32 + nt * 8 + g;
                        bf[nt][0] = *(const uint32_t*)(Bb + (nn * SK + kc) * 2);
                        bf[nt][1] = *(const uint32_t*)(Bb + (nn * SK + kc + 8) * 2);
                    }
                    #pragma unroll
                    for (int mt = 0; mt < 4; mt++)
                        #pragma unroll
                        for (int nt = 0; nt < 4; nt++)
                            mma16816(d[mt][nt], af[mt], bf[nt]);
                }
            }
        }
        __syncthreads();                         // tiles rewritten next chunk
    }

    // ---- fused row norms: combine the four 16-col partials per row --------
    float* RSS = (float*)(smem + SM_RSS);
    float* RS  = (float*)(smem + SM_RS);
    float* AS  = (float*)(smem + SM_AS);
    float* CS  = (float*)(smem + SM_CS);
    RSS[arow * 4 + (tid & 3)] = ssq;
    if (tid < BR) RS[tid] = 0.0f;
    if (tid < KT) CS[tid] = 0.0f;
    __syncthreads();
    float scv[4][2];
    #pragma unroll
    for (int mt = 0; mt < 4; mt++) {
        int rlo = mt * 16 + g, rhi = rlo + 8;
        scv[mt][0] = rsqrtf(fmaxf(RSS[rlo * 4] + RSS[rlo * 4 + 1] + RSS[rlo * 4 + 2] + RSS[rlo * 4 + 3], 1e-12f)) * TINV;
        scv[mt][1] = rsqrtf(fmaxf(RSS[rhi * 4] + RSS[rhi * 4 + 1] + RSS[rhi * 4 + 2] + RSS[rhi * 4 + 3], 1e-12f)) * TINV;
    }
    __syncthreads();

    // ---- epilogue: exp + rowsum + stage; coalesced E store + colsum -------
    float* stg = (float*)smem;                   // [64][260], overlays tiles
    #pragma unroll
    for (int mt = 0; mt < 4; mt++) {
        int rlo = mt * 16 + g, rhi = rlo + 8;
        float slo = scv[mt][0], shi = scv[mt][1];
        float rs0 = 0.0f, rs1 = 0.0f;
        #pragma unroll
        for (int nt = 0; nt < 4; nt++) {
            int nn = w * 32 + nt * 8 + q * 2;
            float e0 = __expf(d[mt][nt][0] * slo);
            float e1 = __expf(d[mt][nt][1] * slo);
            float e2 = __expf(d[mt][nt][2] * shi);
            float e3 = __expf(d[mt][nt][3] * shi);
            rs0 += e0 + e1; rs1 += e2 + e3;
            *(float2*)(stg + rlo * STG_S + nn) = make_float2(e0, e1);
            *(float2*)(stg + rhi * STG_S + nn) = make_float2(e2, e3);
        }
        atomicAdd(&RS[rlo], rs0); atomicAdd(&RS[rhi], rs1);
    }
    __syncthreads();
    if (tid < BR) AS[tid] = 1.0f / ((float)n * RS[tid]);
    __syncthreads();
    {
        int rr = tid >> 6, cc = (tid & 63) * 4;
        float c0 = 0, c1 = 0, c2 = 0, c3 = 0;
        #pragma unroll 4
        for (int rb = 0; rb < 16; rb++) {
            int r = rb * 4 + rr;
            float4 v = *(const float4*)(stg + r * STG_S + cc);
            *(float4*)(g_E + (size_t)(r0 + r) * KT + cc) = v;
            float a = AS[r];
            c0 += a * v.x; c1 += a * v.y; c2 += a * v.z; c3 += a * v.w;
        }
        atomicAdd(&CS[cc + 0], c0); atomicAdd(&CS[cc + 1], c1);
        atomicAdd(&CS[cc + 2], c2); atomicAdd(&CS[cc + 3], c3);
        __syncthreads();
        if (tid < KT) atomicAdd(&g_cs1[tid], CS[tid]);
    }
}

// ---- sinkhorn pass: cp.async double-buffered 32-row tiles -----------------
#define PTILE 32
#define PASS_SMEM ((2 * PTILE * KT + KT) * 4)

template<int P>
__global__ __launch_bounds__(256, 3) void k_pass(int n) {
    const float* ci = (P == 1) ? g_cs1 : g_cs2; float* co = (P == 1) ? g_cs2 : g_cs3;
    extern __shared__ float pbuf[];
    float* sa = pbuf + 2 * PTILE * KT;
    int tid = threadIdx.x, lane = tid & 31, w = tid >> 5;
    uint32_t sbb[2];
    sbb[0] = (uint32_t)__cvta_generic_to_shared(pbuf);
    sbb[1] = (uint32_t)__cvta_generic_to_shared(pbuf + PTILE * KT);

    float bb[8];
    #pragma unroll
    for (int j = 0; j < 8; j++) bb[j] = 1.0f / ((float)KT * ci[lane + 32 * j]);
    float ca[8] = {0, 0, 0, 0, 0, 0, 0, 0};
    float ninv = 1.0f / (float)n;
    int ntiles = n >> 5;

    {
        const float* src = g_E + (size_t)blockIdx.x * PTILE * KT;
        #pragma unroll
        for (int i = 0; i < 8; i++) cpa16(sbb[0] + (tid + i * 256) * 16, src + (tid + i * 256) * 4);
        cpacm();
    }
    int it = 0;
    for (int t = blockIdx.x; t < ntiles; t += gridDim.x, it++) {
        int st = it & 1;
        int nt = t + gridDim.x;
        if (nt < ntiles) {
            const float* src = g_E + (size_t)nt * PTILE * KT;
            #pragma unroll
            for (int i = 0; i < 8; i++) cpa16(sbb[st ^ 1] + (tid + i * 256) * 16, src + (tid + i * 256) * 4);
        }
        cpacm();
        cpaw<1>();
        __syncthreads();
        const float* B = pbuf + st * PTILE * KT;
        #pragma unroll
        for (int r = 0; r < 4; r++) {
            int row = w * 4 + r;
            float v[8];
            #pragma unroll
            for (int j = 0; j < 8; j++) v[j] = B[row * KT + lane + 32 * j];
            float s = v[0] * bb[0] + v[1] * bb[1] + v[2] * bb[2] + v[3] * bb[3]
                    + v[4] * bb[4] + v[5] * bb[5] + v[6] * bb[6] + v[7] * bb[7];
            #pragma unroll
            for (int o = 16; o; o >>= 1) s += __shfl_xor_sync(0xffffffffu, s, o);
            float a = ninv / s;
            #pragma unroll
            for (int j = 0; j < 8; j++) ca[j] += a * v[j];
        }
        __syncthreads();
    }
    if (tid < KT) sa[tid] = 0.0f;
    __syncthreads();
    #pragma unroll
    for (int j = 0; j < 8; j++) atomicAdd(&sa[lane + 32 * j], ca[j]);
    __syncthreads();
    if (tid < KT) atomicAdd(&co[tid], sa[tid]);
}

__global__ void k_final(const float* __restrict__ x, float* __restrict__ out, int n) {
    int lane = threadIdx.x & 31, warp = (blockIdx.x * blockDim.x + threadIdx.x) >> 5, nw = (gridDim.x * blockDim.x) >> 5;
    float bb[8];
    #pragma unroll
    for (int j = 0; j < 8; j++) bb[j] = 1.0f / ((float)KT * g_cs3[lane * 8 + j]);
    for (int rg = warp * 4; rg < n; rg += nw * 4) {
        float4 e[4][2];
        #pragma unroll
        for (int r = 0; r < 4; r++) {
            const float4* er = (const float4*)(g_E + (size_t)(rg + r) * KT) + lane * 2;
            e[r][0] = er[0]; e[r][1] = er[1];
        }
        #pragma unroll
        for (int r = 0; r < 4; r++) {
            int row = rg + r;
            float v[8] = { e[r][0].x * bb[0], e[r][0].y * bb[1], e[r][0].z * bb[2], e[r][0].w * bb[3],
                           e[r][1].x * bb[4], e[r][1].y * bb[5], e[r][1].z * bb[6], e[r][1].w * bb[7] };
            float best = v[0]; int bi = lane * 8;
            #pragma unroll
            for (int j = 1; j < 8; j++) if (v[j] > best) { best = v[j]; bi = lane * 8 + j; }
            #pragma unroll
            for (int o = 1; o < 16; o <<= 1) {
                float ob = __shfl_xor_sync(0xffffffffu, best, o);
                int  obi = __shfl_xor_sync(0xffffffffu, bi, o);
                if (ob > best || (ob == best && obi < bi)) { best = ob; bi = obi; }
            }
            int lidx = __shfl_sync(0xffffffffu, bi, 0);
            int gidx = __shfl_sync(0xffffffffu, bi, 16) - MM;
            if (lane == 0) atomicMax(&g_lastIdx[lidx], row);
            const float* xr = x + (size_t)row * DD;
            const float* gt = g_gated + (size_t)gidx * DD;
            float o6[6]; float ss = 0.0f;
            #pragma unroll
            for (int k = 0; k < 6; k++) { float ov = 0.5f * (gt[lane + 32 * k] + xr[lane + 32 * k]); o6[k] = ov; ss += ov * ov; }
            #pragma unroll
            for (int o = 16; o; o >>= 1) ss += __shfl_xor_sync(0xffffffffu, ss, o);
            float rinv = rsqrtf(fmaxf(ss, 1e-12f));
            float* orow = out + (size_t)row * DD;
            #pragma unroll
            for (int k = 0; k < 6; k++) orow[lane + 32 * k] = o6[k] * rinv;
        }
    }
}

__global__ void k_ema(const float* __restrict__ x, const float* __restrict__ localP,
                      float* __restrict__ outLocal) {
    int m = blockIdx.x, t = threadIdx.x;
    int i = g_lastIdx[m];
    float lv = localP[m * DD + t];
    outLocal[m * DD + t] = (i >= 0) ? (0.96f * lv + 0.04f * x[(size_t)i * DD + t]) : lv;
}

extern "C" void kernel_launch(void* const* d_in, const int* in_sizes, int n_in,
                              void* d_out, int out_size) {
    const float* proj = (const float*)d_in[0];
    const float* localP = (const float*)d_in[1];
    const float* globalP = (const float*)d_in[2];
    const float* W = (const float*)d_in[3];
    const float* bias = (const float*)d_in[4];
    float* out = (float*)d_out;
    int n = in_sizes[0] / DD;
    float* outLocal = out + (size_t)in_sizes[0];

    cudaFuncSetAttribute(k_tc, cudaFuncAttributeMaxDynamicSharedMemorySize, SMEMTOT);
    cudaFuncSetAttribute(k_pass<1>, cudaFuncAttributeMaxDynamicSharedMemorySize, PASS_SMEM);
    cudaFuncSetAttribute(k_pass<2>, cudaFuncAttributeMaxDynamicSharedMemorySize, PASS_SMEM);

    k_setup<<<KT + MM + 1, 2 * DD>>>(localP, globalP, W, bias);
    k_tc<<<n / BR, 256, SMEMTOT>>>(proj, n);
    k_pass<1><<<444, 256, PASS_SMEM>>>(n);
    k_pass<2><<<444, 256, PASS_SMEM>>>(n);
    k_final<<<1024, 256>>>(proj, out, n);
    k_ema<<<MM, DD>>>(proj, localP, outLocal);
}